// round 4
// baseline (speedup 1.0000x reference)
#include <cuda_runtime.h>
#include <math.h>

// Problem max sizes (N=50000, E=800000)
#define NMAX 50000
#define EMAX 800000

// ---- static device scratch ----
__device__ float  g_za[NMAX * 64];     // layer-0 z
__device__ float  g_zb[NMAX * 64];     // layer-1 z
__device__ float  g_u[NMAX * 32];      // h1 @ Wm1[0:64]
__device__ float  g_v[NMAX * 32];      // h1 @ Wm1[64:128]
__device__ __align__(16) float g_hdest[64];
__device__ double g_easum[2];
__device__ float  g_eamean[2];
// CSR by dst: packed edge payload {src, perm, ea.x(bits), ea.y(bits)}
__device__ int    g_cnt[NMAX];
__device__ int    g_rowptr[NMAX + 1];
__device__ int    g_rowcur[NMAX];
__device__ int4   g_epack[EMAX];
// decoupled-lookback scan state
__device__ unsigned long long g_tile[256];
__device__ int    g_tilectr;

// ============================================================
// 0) init
// ============================================================
__global__ void k_init(int N) {
    int i = blockIdx.x * blockDim.x + threadIdx.x;
    if (i < N) g_cnt[i] = 0;
    if (i < 256) g_tile[i] = 0ull;
    if (i == 0) { g_tilectr = 0; g_easum[0] = 0.0; g_easum[1] = 0.0; }
}

// ============================================================
// 1) fused: edge_attr column sums (double) + dst histogram
// ============================================================
__global__ void k_easum_hist(const int* __restrict__ ei,
                             const float2* __restrict__ ea, int E) {
    double d0 = 0.0, d1 = 0.0;
    for (int i = blockIdx.x * blockDim.x + threadIdx.x; i < E;
         i += gridDim.x * blockDim.x) {
        float2 v = ea[i];
        d0 += (double)v.x; d1 += (double)v.y;
        atomicAdd(&g_cnt[ei[E + i]], 1);
    }
    __shared__ double sh0[256], sh1[256];
    int t = threadIdx.x;
    sh0[t] = d0; sh1[t] = d1;
    __syncthreads();
    for (int ofs = 128; ofs > 0; ofs >>= 1) {
        if (t < ofs) { sh0[t] += sh0[t + ofs]; sh1[t] += sh1[t + ofs]; }
        __syncthreads();
    }
    if (t == 0) { atomicAdd(&g_easum[0], sh0[0]); atomicAdd(&g_easum[1], sh1[0]); }
}

// ============================================================
// 2) exclusive scan of g_cnt (decoupled lookback) + eamean
// ============================================================
__global__ void __launch_bounds__(256) k_scan(int N, int E) {
    __shared__ int sbid;
    __shared__ int swsum[8];
    __shared__ int sexcl;
    if (threadIdx.x == 0) sbid = atomicAdd(&g_tilectr, 1);
    __syncthreads();
    int bid = sbid;
    if (bid == 0 && threadIdx.x < 2)
        g_eamean[threadIdx.x] = (float)(g_easum[threadIdx.x] / (double)E);

    int i = bid * 256 + threadIdx.x;
    int v = (i < N) ? g_cnt[i] : 0;
    int lane = threadIdx.x & 31, w = threadIdx.x >> 5;
    int s = v;
#pragma unroll
    for (int o = 1; o < 32; o <<= 1) {
        int t = __shfl_up_sync(0xffffffffu, s, o);
        if (lane >= o) s += t;
    }
    if (lane == 31) swsum[w] = s;
    __syncthreads();
    if (w == 0) {
        int ws = (lane < 8) ? swsum[lane] : 0;
#pragma unroll
        for (int o = 1; o < 8; o <<= 1) {
            int t = __shfl_up_sync(0xffffffffu, ws, o);
            if (lane >= o) ws += t;
        }
        if (lane < 8) swsum[lane] = ws;
    }
    __syncthreads();
    int incl = s + (w > 0 ? swsum[w - 1] : 0);
    int btotal = swsum[7];

    if (threadIdx.x == 0) {
        unsigned long long word = (bid == 0)
            ? ((2ull << 32) | (unsigned)btotal)
            : ((1ull << 32) | (unsigned)btotal);
        atomicExch(&g_tile[bid], word);
    }

    if (bid > 0 && w == 0) {
        int excl = 0;
        int look = bid - 1 - lane;
        for (;;) {
            unsigned long long word = (look >= 0)
                ? atomicAdd(&g_tile[look], 0ull) : (2ull << 32);
            unsigned st = (unsigned)(word >> 32);
            unsigned pend = __ballot_sync(0xffffffffu, st == 0u);
            if (pend) continue;
            unsigned pre = __ballot_sync(0xffffffffu, st == 2u);
            int fp = __ffs(pre) - 1;
            int val = (int)(word & 0xffffffffu);
            if (fp >= 0) {
                int contrib = (lane <= fp && look >= 0) ? val : 0;
#pragma unroll
                for (int o = 16; o > 0; o >>= 1)
                    contrib += __shfl_xor_sync(0xffffffffu, contrib, o);
                excl += contrib;
                break;
            } else {
                int contrib = (look >= 0) ? val : 0;
#pragma unroll
                for (int o = 16; o > 0; o >>= 1)
                    contrib += __shfl_xor_sync(0xffffffffu, contrib, o);
                excl += contrib;
                look -= 32;
            }
        }
        if (lane == 0) {
            atomicExch(&g_tile[bid], (2ull << 32) | (unsigned)(excl + btotal));
            sexcl = excl;
        }
    } else if (threadIdx.x == 0) {
        sexcl = 0;
    }
    __syncthreads();
    int excl = sexcl;
    if (i < N) {
        int ip = excl + incl;
        g_rowptr[i + 1] = ip;
        g_rowcur[i] = ip - v;
    }
    if (i == 0) g_rowptr[0] = 0;
}

// ============================================================
// 3) fused: packed CSR scatter + z0 = x@W0+b0
// ============================================================
__global__ void k_scatter_z0(const int* __restrict__ ei,
                             const float2* __restrict__ ea,
                             const float* __restrict__ x,
                             const float* __restrict__ W0,
                             const float* __restrict__ b0,
                             int N, int E, int gE) {
    if ((int)blockIdx.x < gE) {
        int e = blockIdx.x * 256 + threadIdx.x;
        if (e < E) {
            int dst = ei[E + e];
            int pos = atomicAdd(&g_rowcur[dst], 1);
            float2 a = ea[e];
            g_epack[pos] = make_int4(ei[e], e, __float_as_int(a.x),
                                     __float_as_int(a.y));
        }
    } else {
        int i = (blockIdx.x - gE) * 256 + threadIdx.x;
        if (i < N * 64) {
            int n = i >> 6, j = i & 63;
            g_za[i] = fmaf(x[2 * n], W0[j], fmaf(x[2 * n + 1], W0[64 + j], b0[j]));
        }
    }
}

// ============================================================
// GATv2 online-softmax aggregation core.
// Warp = dst node. Half-warps process alternating edge positions.
// lane = pair*16 + q; q: head hh=q>>3, 4 channels ch=hh*32+(q&7)*4.
// Two independent states per lane (unroll 2) -> 4 edges in flight.
// Position t: 0 = virtual self loop; t>0 -> epack[base+t-1].
// ============================================================
__device__ __forceinline__ float4 gat_agg4(const float* __restrict__ zbase,
                                           int dst, int lane, int ch, int pair,
                                           const float* __restrict__ We,
                                           const float* __restrict__ att,
                                           const float* __restrict__ bias) {
    float4 We0 = *(const float4*)&We[ch];
    float4 We1 = *(const float4*)&We[64 + ch];
    float4 at  = *(const float4*)&att[ch];
    float4 zd  = __ldg((const float4*)&zbase[dst * 64 + ch]);
    float eamx = g_eamean[0], eamy = g_eamean[1];

    int base = g_rowptr[dst];
    int total = g_rowptr[dst + 1] - base + 1;   // +1 virtual self loop

    float m1 = -INFINITY, d1 = 0.f, m2 = -INFINITY, d2 = 0.f;
    float4 a1 = make_float4(0, 0, 0, 0), a2 = make_float4(0, 0, 0, 0);

    for (int k0 = 0; k0 < total; k0 += 4) {
        int tA = k0 + pair;
        int tB = k0 + 2 + pair;
        bool vA = tA < total;
        bool vB = tB < total;

        float eaxA = eamx, eayA = eamy; float4 zA = zd;
        if (vA && tA > 0) {
            int4 pk = g_epack[base + tA - 1];
            eaxA = __int_as_float(pk.z); eayA = __int_as_float(pk.w);
            zA = __ldg((const float4*)&zbase[pk.x * 64 + ch]);
        }
        float eaxB = eamx, eayB = eamy; float4 zB = zd;
        if (vB && tB > 0) {
            int4 pk = g_epack[base + tB - 1];
            eaxB = __int_as_float(pk.z); eayB = __int_as_float(pk.w);
            zB = __ldg((const float4*)&zbase[pk.x * 64 + ch]);
        }
        float s, pA, pB;
        s = zd.x + zA.x + fmaf(eaxA, We0.x, eayA * We1.x);
        s = (s > 0.f) ? s : 0.2f * s; pA = s * at.x;
        s = zd.y + zA.y + fmaf(eaxA, We0.y, eayA * We1.y);
        s = (s > 0.f) ? s : 0.2f * s; pA = fmaf(s, at.y, pA);
        s = zd.z + zA.z + fmaf(eaxA, We0.z, eayA * We1.z);
        s = (s > 0.f) ? s : 0.2f * s; pA = fmaf(s, at.z, pA);
        s = zd.w + zA.w + fmaf(eaxA, We0.w, eayA * We1.w);
        s = (s > 0.f) ? s : 0.2f * s; pA = fmaf(s, at.w, pA);

        s = zd.x + zB.x + fmaf(eaxB, We0.x, eayB * We1.x);
        s = (s > 0.f) ? s : 0.2f * s; pB = s * at.x;
        s = zd.y + zB.y + fmaf(eaxB, We0.y, eayB * We1.y);
        s = (s > 0.f) ? s : 0.2f * s; pB = fmaf(s, at.y, pB);
        s = zd.z + zB.z + fmaf(eaxB, We0.z, eayB * We1.z);
        s = (s > 0.f) ? s : 0.2f * s; pB = fmaf(s, at.z, pB);
        s = zd.w + zB.w + fmaf(eaxB, We0.w, eayB * We1.w);
        s = (s > 0.f) ? s : 0.2f * s; pB = fmaf(s, at.w, pB);

        // reduce within 8-lane head groups (xor 4,2,1 stays in group)
#pragma unroll
        for (int o = 4; o >= 1; o >>= 1) {
            pA += __shfl_xor_sync(0xffffffffu, pA, o);
            pB += __shfl_xor_sync(0xffffffffu, pB, o);
        }
        if (vA) {
            float mn = fmaxf(m1, pA);
            float sc = __expf(m1 - mn);
            float w  = __expf(pA - mn);
            d1 = fmaf(d1, sc, w);
            a1.x = fmaf(a1.x, sc, w * zA.x);
            a1.y = fmaf(a1.y, sc, w * zA.y);
            a1.z = fmaf(a1.z, sc, w * zA.z);
            a1.w = fmaf(a1.w, sc, w * zA.w);
            m1 = mn;
        }
        if (vB) {
            float mn = fmaxf(m2, pB);
            float sc = __expf(m2 - mn);
            float w  = __expf(pB - mn);
            d2 = fmaf(d2, sc, w);
            a2.x = fmaf(a2.x, sc, w * zB.x);
            a2.y = fmaf(a2.y, sc, w * zB.y);
            a2.z = fmaf(a2.z, sc, w * zB.z);
            a2.w = fmaf(a2.w, sc, w * zB.w);
            m2 = mn;
        }
    }
    // merge state2 into state1 (guard empty states: d==0)
    {
        float mn = fmaxf(m1, m2);
        float s1 = (d1 > 0.f) ? __expf(m1 - mn) : 0.f;
        float s2 = (d2 > 0.f) ? __expf(m2 - mn) : 0.f;
        d1 = d1 * s1 + d2 * s2;
        a1.x = a1.x * s1 + a2.x * s2;
        a1.y = a1.y * s1 + a2.y * s2;
        a1.z = a1.z * s1 + a2.z * s2;
        a1.w = a1.w * s1 + a2.w * s2;
        m1 = mn;
    }
    // merge across half-warps (xor 16)
    {
        float pm = __shfl_xor_sync(0xffffffffu, m1, 16);
        float pd = __shfl_xor_sync(0xffffffffu, d1, 16);
        float px = __shfl_xor_sync(0xffffffffu, a1.x, 16);
        float py = __shfl_xor_sync(0xffffffffu, a1.y, 16);
        float pz = __shfl_xor_sync(0xffffffffu, a1.z, 16);
        float pw = __shfl_xor_sync(0xffffffffu, a1.w, 16);
        float mn = fmaxf(m1, pm);
        float sa = (d1 > 0.f) ? __expf(m1 - mn) : 0.f;
        float sb = (pd > 0.f) ? __expf(pm - mn) : 0.f;
        d1 = d1 * sa + pd * sb;
        a1.x = a1.x * sa + px * sb;
        a1.y = a1.y * sa + py * sb;
        a1.z = a1.z * sa + pz * sb;
        a1.w = a1.w * sa + pw * sb;
    }
    float inv = __fdividef(1.f, d1 + 1e-16f);
    float4 b4 = *(const float4*)&bias[ch];
    float4 h;
    float o;
    o = fmaf(a1.x, inv, b4.x); h.x = (o > 0.f) ? o : expm1f(o);
    o = fmaf(a1.y, inv, b4.y); h.y = (o > 0.f) ? o : expm1f(o);
    o = fmaf(a1.z, inv, b4.z); h.z = (o > 0.f) ? o : expm1f(o);
    o = fmaf(a1.w, inv, b4.w); h.w = (o > 0.f) ? o : expm1f(o);
    return h;
}

// ============================================================
// 4) layer 0: agg + ELU + fused z1 = h@W1+b1
// ============================================================
__global__ void __launch_bounds__(256)
k_agg0(const float* __restrict__ We, const float* __restrict__ att,
       const float* __restrict__ bias,
       const float* __restrict__ W1, const float* __restrict__ b1, int N) {
    __shared__ float sW[64 * 64];
    __shared__ __align__(16) float sh[8][64];
    for (int i = threadIdx.x; i < 64 * 64; i += blockDim.x) sW[i] = W1[i];
    __syncthreads();

    int warp = (blockIdx.x * blockDim.x + threadIdx.x) >> 5;
    int lane = threadIdx.x & 31;
    int ws = threadIdx.x >> 5;
    bool active = warp < N;
    int dst = active ? warp : 0;
    int pair = lane >> 4;
    int q = lane & 15;
    int ch = (q >> 3) * 32 + (q & 7) * 4;

    float4 h = gat_agg4(g_za, dst, lane, ch, pair, We, att, bias);

    if (pair == 0) *(float4*)&sh[ws][ch] = h;
    __syncwarp();
    int c = lane * 2;
    float za = b1[c], zb = b1[c + 1];
#pragma unroll
    for (int k = 0; k < 64; k++) {
        float hv = sh[ws][k];
        float2 w2 = *(const float2*)&sW[k * 64 + c];
        za = fmaf(hv, w2.x, za);
        zb = fmaf(hv, w2.y, zb);
    }
    if (active) {
        g_zb[dst * 64 + c]     = za;
        g_zb[dst * 64 + c + 1] = zb;
    }
}

// ============================================================
// 5) layer 1: agg + ELU + fused u/v = h@Wm1[0:128] + goal capture
// ============================================================
__global__ void __launch_bounds__(256)
k_agg1(const float* __restrict__ We, const float* __restrict__ att,
       const float* __restrict__ bias,
       const float* __restrict__ Wm1, const int* __restrict__ destp, int N) {
    __shared__ float sW[128 * 32];
    __shared__ __align__(16) float sh[8][64];
    for (int i = threadIdx.x; i < 128 * 32; i += blockDim.x) sW[i] = Wm1[i];
    __syncthreads();

    int warp = (blockIdx.x * blockDim.x + threadIdx.x) >> 5;
    int lane = threadIdx.x & 31;
    int ws = threadIdx.x >> 5;
    bool active = warp < N;
    int dst = active ? warp : 0;
    int pair = lane >> 4;
    int q = lane & 15;
    int ch = (q >> 3) * 32 + (q & 7) * 4;

    float4 h = gat_agg4(g_zb, dst, lane, ch, pair, We, att, bias);

    if (pair == 0) {
        *(float4*)&sh[ws][ch] = h;
        if (active && dst == destp[0]) *(float4*)&g_hdest[ch] = h;
    }
    __syncwarp();
    float ua = 0.f, va = 0.f;
#pragma unroll
    for (int k = 0; k < 64; k++) {
        float hv = sh[ws][k];
        ua = fmaf(hv, sW[k * 32 + lane], ua);
        va = fmaf(hv, sW[(64 + k) * 32 + lane], va);
    }
    if (active) {
        g_u[dst * 32 + lane] = ua;
        g_v[dst * 32 + lane] = va;
    }
}

// ============================================================
// 6) edge MLP, warp per dst node in CSR order (gvec folded in).
// lane = hidden channel.
// ============================================================
__global__ void __launch_bounds__(256)
k_edge(const float* __restrict__ Wm1, const float* __restrict__ bm1,
       const float* __restrict__ Wm2, const float* __restrict__ bm2,
       float* __restrict__ out, int N) {
    __shared__ float sg[32];
    if (threadIdx.x < 32) {
        int j = threadIdx.x;
        float acc = bm1[j];
#pragma unroll
        for (int k = 0; k < 64; k++)
            acc = fmaf(g_hdest[k], Wm1[(128 + k) * 32 + j], acc);
        sg[j] = acc;
    }
    __syncthreads();

    int warp = (blockIdx.x * blockDim.x + threadIdx.x) >> 5;
    int lane = threadIdx.x & 31;
    if (warp >= N) return;
    int dst = warp;
    float vl = g_v[dst * 32 + lane];
    float gl = sg[lane];
    float w192 = Wm1[192 * 32 + lane];
    float w193 = Wm1[193 * 32 + lane];
    float w2 = Wm2[lane];
    float bm2v = bm2[0];
    float base_l = vl + gl;

    int idx = g_rowptr[dst], end = g_rowptr[dst + 1];
    for (; idx + 2 <= end; idx += 2) {
        int4 p1 = g_epack[idx];
        int4 p2 = g_epack[idx + 1];
        float u1 = __ldg(&g_u[p1.x * 32 + lane]);
        float u2 = __ldg(&g_u[p2.x * 32 + lane]);
        float h1 = u1 + base_l + fmaf(__int_as_float(p1.z), w192,
                                      __int_as_float(p1.w) * w193);
        float h2 = u2 + base_l + fmaf(__int_as_float(p2.z), w192,
                                      __int_as_float(p2.w) * w193);
        float s1 = fmaxf(h1, 0.f) * w2;
        float s2 = fmaxf(h2, 0.f) * w2;
#pragma unroll
        for (int o = 16; o >= 1; o >>= 1) {
            s1 += __shfl_xor_sync(0xffffffffu, s1, o);
            s2 += __shfl_xor_sync(0xffffffffu, s2, o);
        }
        if (lane == 0) {
            out[p1.y] = s1 + bm2v;
            out[p2.y] = s2 + bm2v;
        }
    }
    if (idx < end) {
        int4 p1 = g_epack[idx];
        float u1 = __ldg(&g_u[p1.x * 32 + lane]);
        float h1 = u1 + base_l + fmaf(__int_as_float(p1.z), w192,
                                      __int_as_float(p1.w) * w193);
        float s1 = fmaxf(h1, 0.f) * w2;
#pragma unroll
        for (int o = 16; o >= 1; o >>= 1)
            s1 += __shfl_xor_sync(0xffffffffu, s1, o);
        if (lane == 0) out[p1.y] = s1 + bm2v;
    }
}

// ============================================================
extern "C" void kernel_launch(void* const* d_in, const int* in_sizes, int n_in,
                              void* d_out, int out_size) {
    const float* x     = (const float*)d_in[0];
    const int*   ei    = (const int*)d_in[1];
    const float* ea    = (const float*)d_in[2];
    const int*   dest  = (const int*)d_in[3];
    const float* W0    = (const float*)d_in[4];
    const float* b0    = (const float*)d_in[5];
    const float* We0   = (const float*)d_in[6];
    const float* att0  = (const float*)d_in[7];
    const float* bias0 = (const float*)d_in[8];
    const float* W1    = (const float*)d_in[9];
    const float* b1    = (const float*)d_in[10];
    const float* We1   = (const float*)d_in[11];
    const float* att1  = (const float*)d_in[12];
    const float* bias1 = (const float*)d_in[13];
    const float* Wm1   = (const float*)d_in[14];
    const float* bm1   = (const float*)d_in[15];
    const float* Wm2   = (const float*)d_in[16];
    const float* bm2   = (const float*)d_in[17];

    int N = in_sizes[0] / 2;
    int E = in_sizes[1] / 2;

    const int TB = 256;
    int gN   = (N + TB - 1) / TB;
    int gE   = (E + TB - 1) / TB;
    int gN64 = (N * 64 + TB - 1) / TB;
    int gAgg = (N * 32 + TB - 1) / TB;
    int nSB  = (N + 255) / 256;
    int gInit = (gN > 1) ? gN : 1;

    k_init<<<gInit, TB>>>(N);                                           // 0
    k_easum_hist<<<512, TB>>>(ei, (const float2*)ea, E);                // 1
    k_scan<<<nSB, 256>>>(N, E);                                         // 2
    k_scatter_z0<<<gE + gN64, TB>>>(ei, (const float2*)ea, x,
                                    W0, b0, N, E, gE);                  // 3
    k_agg0<<<gAgg, TB>>>(We0, att0, bias0, W1, b1, N);                  // 4
    k_agg1<<<gAgg, TB>>>(We1, att1, bias1, Wm1, dest, N);               // 5
    k_edge<<<gAgg, TB>>>(Wm1, bm1, Wm2, bm2, (float*)d_out, N);         // 6
}

// round 5
// speedup vs baseline: 1.1035x; 1.1035x over previous
#include <cuda_runtime.h>
#include <math.h>

// Problem max sizes (N=50000, E=800000)
#define NMAX 50000
#define EMAX 800000

// ---- static device scratch ----
__device__ float  g_za[NMAX * 64];     // layer-0 z
__device__ float  g_zb[NMAX * 64];     // layer-1 z
__device__ float  g_u[NMAX * 32];      // h1 @ Wm1[0:64]
__device__ float  g_v[NMAX * 32];      // h1 @ Wm1[64:128]
__device__ __align__(16) float g_hdest[64];
__device__ double g_easum[2];
__device__ float  g_eamean[2];
// CSR by dst: packed edge payload {src, perm, ea.x(bits), ea.y(bits)}
__device__ int    g_cnt[NMAX];
__device__ int    g_rowptr[NMAX + 1];
__device__ int    g_rowcur[NMAX];
__device__ int4   g_epack[EMAX];
// decoupled-lookback scan state
__device__ unsigned long long g_tile[256];
__device__ int    g_tilectr;

// ============================================================
// 0) init
// ============================================================
__global__ void k_init(int N) {
    int i = blockIdx.x * blockDim.x + threadIdx.x;
    if (i < N) g_cnt[i] = 0;
    if (i < 256) g_tile[i] = 0ull;
    if (i == 0) { g_tilectr = 0; g_easum[0] = 0.0; g_easum[1] = 0.0; }
}

// ============================================================
// 1) fused: edge_attr column sums (double) + dst histogram
// ============================================================
__global__ void k_easum_hist(const int* __restrict__ ei,
                             const float2* __restrict__ ea, int E) {
    double d0 = 0.0, d1 = 0.0;
    for (int i = blockIdx.x * blockDim.x + threadIdx.x; i < E;
         i += gridDim.x * blockDim.x) {
        float2 v = ea[i];
        d0 += (double)v.x; d1 += (double)v.y;
        atomicAdd(&g_cnt[ei[E + i]], 1);
    }
    __shared__ double sh0[256], sh1[256];
    int t = threadIdx.x;
    sh0[t] = d0; sh1[t] = d1;
    __syncthreads();
    for (int ofs = 128; ofs > 0; ofs >>= 1) {
        if (t < ofs) { sh0[t] += sh0[t + ofs]; sh1[t] += sh1[t + ofs]; }
        __syncthreads();
    }
    if (t == 0) { atomicAdd(&g_easum[0], sh0[0]); atomicAdd(&g_easum[1], sh1[0]); }
}

// ============================================================
// 2) exclusive scan of g_cnt (decoupled lookback) + eamean
// ============================================================
__global__ void __launch_bounds__(256) k_scan(int N, int E) {
    __shared__ int sbid;
    __shared__ int swsum[8];
    __shared__ int sexcl;
    if (threadIdx.x == 0) sbid = atomicAdd(&g_tilectr, 1);
    __syncthreads();
    int bid = sbid;
    if (bid == 0 && threadIdx.x < 2)
        g_eamean[threadIdx.x] = (float)(g_easum[threadIdx.x] / (double)E);

    int i = bid * 256 + threadIdx.x;
    int v = (i < N) ? g_cnt[i] : 0;
    int lane = threadIdx.x & 31, w = threadIdx.x >> 5;
    int s = v;
#pragma unroll
    for (int o = 1; o < 32; o <<= 1) {
        int t = __shfl_up_sync(0xffffffffu, s, o);
        if (lane >= o) s += t;
    }
    if (lane == 31) swsum[w] = s;
    __syncthreads();
    if (w == 0) {
        int ws = (lane < 8) ? swsum[lane] : 0;
#pragma unroll
        for (int o = 1; o < 8; o <<= 1) {
            int t = __shfl_up_sync(0xffffffffu, ws, o);
            if (lane >= o) ws += t;
        }
        if (lane < 8) swsum[lane] = ws;
    }
    __syncthreads();
    int incl = s + (w > 0 ? swsum[w - 1] : 0);
    int btotal = swsum[7];

    if (threadIdx.x == 0) {
        unsigned long long word = (bid == 0)
            ? ((2ull << 32) | (unsigned)btotal)
            : ((1ull << 32) | (unsigned)btotal);
        atomicExch(&g_tile[bid], word);
    }

    if (bid > 0 && w == 0) {
        int excl = 0;
        int look = bid - 1 - lane;
        for (;;) {
            unsigned long long word = (look >= 0)
                ? atomicAdd(&g_tile[look], 0ull) : (2ull << 32);
            unsigned st = (unsigned)(word >> 32);
            unsigned pend = __ballot_sync(0xffffffffu, st == 0u);
            if (pend) continue;
            unsigned pre = __ballot_sync(0xffffffffu, st == 2u);
            int fp = __ffs(pre) - 1;
            int val = (int)(word & 0xffffffffu);
            if (fp >= 0) {
                int contrib = (lane <= fp && look >= 0) ? val : 0;
#pragma unroll
                for (int o = 16; o > 0; o >>= 1)
                    contrib += __shfl_xor_sync(0xffffffffu, contrib, o);
                excl += contrib;
                break;
            } else {
                int contrib = (look >= 0) ? val : 0;
#pragma unroll
                for (int o = 16; o > 0; o >>= 1)
                    contrib += __shfl_xor_sync(0xffffffffu, contrib, o);
                excl += contrib;
                look -= 32;
            }
        }
        if (lane == 0) {
            atomicExch(&g_tile[bid], (2ull << 32) | (unsigned)(excl + btotal));
            sexcl = excl;
        }
    } else if (threadIdx.x == 0) {
        sexcl = 0;
    }
    __syncthreads();
    int excl = sexcl;
    if (i < N) {
        int ip = excl + incl;
        g_rowptr[i + 1] = ip;
        g_rowcur[i] = ip - v;
    }
    if (i == 0) g_rowptr[0] = 0;
}

// ============================================================
// 3) fused: packed CSR scatter + z0 = x@W0+b0
// ============================================================
__global__ void k_scatter_z0(const int* __restrict__ ei,
                             const float2* __restrict__ ea,
                             const float* __restrict__ x,
                             const float* __restrict__ W0,
                             const float* __restrict__ b0,
                             int N, int E, int gE) {
    if ((int)blockIdx.x < gE) {
        int e = blockIdx.x * 256 + threadIdx.x;
        if (e < E) {
            int dst = ei[E + e];
            int pos = atomicAdd(&g_rowcur[dst], 1);
            float2 a = ea[e];
            g_epack[pos] = make_int4(ei[e], e, __float_as_int(a.x),
                                     __float_as_int(a.y));
        }
    } else {
        int i = (blockIdx.x - gE) * 256 + threadIdx.x;
        if (i < N * 64) {
            int n = i >> 6, j = i & 63;
            g_za[i] = fmaf(x[2 * n], W0[j], fmaf(x[2 * n + 1], W0[64 + j], b0[j]));
        }
    }
}

// ============================================================
// GATv2 online-softmax aggregation core (R3 layout, epack source).
// Warp per dst node; lane handles channels c=2l,2l+1; heads split
// at lane 16. Unrolled by 2 edges for ILP.
// ============================================================
__device__ __forceinline__ void gat_agg(const float* __restrict__ zbase,
                                        int dst, int lane, int c,
                                        const float* __restrict__ We,
                                        const float* __restrict__ att,
                                        const float* __restrict__ bias,
                                        float& h0, float& h1) {
    float We0a = We[c],      We0b = We[c + 1];
    float We1a = We[64 + c], We1b = We[64 + c + 1];
    float at0 = att[c], at1 = att[c + 1];
    float2 zd = __ldg((const float2*)&zbase[dst * 64 + c]);

    // self loop (src=dst, ea=mean)
    float eax = g_eamean[0], eay = g_eamean[1];
    float s0 = zd.x + zd.x + fmaf(eax, We0a, eay * We1a);
    float s1 = zd.y + zd.y + fmaf(eax, We0b, eay * We1b);
    s0 = (s0 > 0.f) ? s0 : 0.2f * s0;
    s1 = (s1 > 0.f) ? s1 : 0.2f * s1;
    float p = fmaf(s0, at0, s1 * at1);
#pragma unroll
    for (int o = 8; o >= 1; o >>= 1) p += __shfl_xor_sync(0xffffffffu, p, o);
    float m = p, denom = 1.f, acc0 = zd.x, acc1 = zd.y;

    int idx = g_rowptr[dst], end = g_rowptr[dst + 1];
    for (; idx + 2 <= end; idx += 2) {
        int4 p1 = g_epack[idx];
        int4 p2 = g_epack[idx + 1];
        float2 za = __ldg((const float2*)&zbase[p1.x * 64 + c]);
        float2 zb = __ldg((const float2*)&zbase[p2.x * 64 + c]);
        float eaAx = __int_as_float(p1.z), eaAy = __int_as_float(p1.w);
        float eaBx = __int_as_float(p2.z), eaBy = __int_as_float(p2.w);

        float a0 = zd.x + za.x + fmaf(eaAx, We0a, eaAy * We1a);
        float a1 = zd.y + za.y + fmaf(eaAx, We0b, eaAy * We1b);
        float b0_ = zd.x + zb.x + fmaf(eaBx, We0a, eaBy * We1a);
        float b1_ = zd.y + zb.y + fmaf(eaBx, We0b, eaBy * We1b);
        a0 = (a0 > 0.f) ? a0 : 0.2f * a0;
        a1 = (a1 > 0.f) ? a1 : 0.2f * a1;
        b0_ = (b0_ > 0.f) ? b0_ : 0.2f * b0_;
        b1_ = (b1_ > 0.f) ? b1_ : 0.2f * b1_;
        float pa = fmaf(a0, at0, a1 * at1);
        float pb = fmaf(b0_, at0, b1_ * at1);
#pragma unroll
        for (int o = 8; o >= 1; o >>= 1) {
            pa += __shfl_xor_sync(0xffffffffu, pa, o);
            pb += __shfl_xor_sync(0xffffffffu, pb, o);
        }
        float mn = fmaxf(m, fmaxf(pa, pb));
        float sc = __expf(m - mn);
        float wa = __expf(pa - mn);
        float wb = __expf(pb - mn);
        denom = fmaf(denom, sc, wa + wb);
        acc0 = fmaf(acc0, sc, fmaf(wa, za.x, wb * zb.x));
        acc1 = fmaf(acc1, sc, fmaf(wa, za.y, wb * zb.y));
        m = mn;
    }
    if (idx < end) {
        int4 p1 = g_epack[idx];
        float2 za = __ldg((const float2*)&zbase[p1.x * 64 + c]);
        float eaAx = __int_as_float(p1.z), eaAy = __int_as_float(p1.w);
        float a0 = zd.x + za.x + fmaf(eaAx, We0a, eaAy * We1a);
        float a1 = zd.y + za.y + fmaf(eaAx, We0b, eaAy * We1b);
        a0 = (a0 > 0.f) ? a0 : 0.2f * a0;
        a1 = (a1 > 0.f) ? a1 : 0.2f * a1;
        float pa = fmaf(a0, at0, a1 * at1);
#pragma unroll
        for (int o = 8; o >= 1; o >>= 1) pa += __shfl_xor_sync(0xffffffffu, pa, o);
        float mn = fmaxf(m, pa);
        float sc = __expf(m - mn);
        float wa = __expf(pa - mn);
        denom = fmaf(denom, sc, wa);
        acc0 = fmaf(acc0, sc, wa * za.x);
        acc1 = fmaf(acc1, sc, wa * za.y);
        m = mn;
    }
    float inv = __fdividef(1.f, denom + 1e-16f);
    float o0 = fmaf(acc0, inv, bias[c]);
    float o1 = fmaf(acc1, inv, bias[c + 1]);
    h0 = (o0 > 0.f) ? o0 : expm1f(o0);
    h1 = (o1 > 0.f) ? o1 : expm1f(o1);
}

// ============================================================
// 4) layer 0: agg + ELU + fused z1 = h@W1+b1
// ============================================================
__global__ void __launch_bounds__(256)
k_agg0(const float* __restrict__ We, const float* __restrict__ att,
       const float* __restrict__ bias,
       const float* __restrict__ W1, const float* __restrict__ b1, int N) {
    __shared__ float sW[64 * 64];
    __shared__ float sh[8][64];
    for (int i = threadIdx.x; i < 64 * 64; i += blockDim.x) sW[i] = W1[i];
    __syncthreads();

    int warp = (blockIdx.x * blockDim.x + threadIdx.x) >> 5;
    int lane = threadIdx.x & 31;
    int ws = threadIdx.x >> 5;
    bool active = warp < N;
    int dst = active ? warp : 0;
    int c = lane * 2;

    float h0, h1;
    gat_agg(g_za, dst, lane, c, We, att, bias, h0, h1);

    sh[ws][c] = h0; sh[ws][c + 1] = h1;
    __syncwarp();
    float za = b1[c], zb = b1[c + 1];
#pragma unroll
    for (int k = 0; k < 64; k++) {
        float hv = sh[ws][k];
        float2 w2 = *(const float2*)&sW[k * 64 + c];
        za = fmaf(hv, w2.x, za);
        zb = fmaf(hv, w2.y, zb);
    }
    if (active) {
        g_zb[dst * 64 + c]     = za;
        g_zb[dst * 64 + c + 1] = zb;
    }
}

// ============================================================
// 5) layer 1: agg + ELU + fused u/v = h@Wm1[0:128] + goal capture
// ============================================================
__global__ void __launch_bounds__(256)
k_agg1(const float* __restrict__ We, const float* __restrict__ att,
       const float* __restrict__ bias,
       const float* __restrict__ Wm1, const int* __restrict__ destp, int N) {
    __shared__ float sW[128 * 32];
    __shared__ float sh[8][64];
    for (int i = threadIdx.x; i < 128 * 32; i += blockDim.x) sW[i] = Wm1[i];
    __syncthreads();

    int warp = (blockIdx.x * blockDim.x + threadIdx.x) >> 5;
    int lane = threadIdx.x & 31;
    int ws = threadIdx.x >> 5;
    bool active = warp < N;
    int dst = active ? warp : 0;
    int c = lane * 2;

    float h0, h1;
    gat_agg(g_zb, dst, lane, c, We, att, bias, h0, h1);

    if (active && dst == destp[0]) {
        g_hdest[c] = h0; g_hdest[c + 1] = h1;
    }

    sh[ws][c] = h0; sh[ws][c + 1] = h1;
    __syncwarp();
    float ua = 0.f, va = 0.f;
#pragma unroll
    for (int k = 0; k < 64; k++) {
        float hv = sh[ws][k];
        ua = fmaf(hv, sW[k * 32 + lane], ua);
        va = fmaf(hv, sW[(64 + k) * 32 + lane], va);
    }
    if (active) {
        g_u[dst * 32 + lane] = ua;
        g_v[dst * 32 + lane] = va;
    }
}

// ============================================================
// 6) edge MLP, warp per dst node, 4 edges x 8 lanes per iteration.
// lane = g*8 + l; group g = edge slot, l = 4-channel block.
// v[dst] + gvec hoisted out of the loop; 3 shuffle levels per edge.
// ============================================================
__global__ void __launch_bounds__(256)
k_edge(const float* __restrict__ Wm1, const float* __restrict__ bm1,
       const float* __restrict__ Wm2, const float* __restrict__ bm2,
       float* __restrict__ out, int N) {
    __shared__ float sg[32];
    if (threadIdx.x < 32) {
        int j = threadIdx.x;
        float acc = bm1[j];
#pragma unroll
        for (int k = 0; k < 64; k++)
            acc = fmaf(g_hdest[k], Wm1[(128 + k) * 32 + j], acc);
        sg[j] = acc;
    }
    __syncthreads();

    int warp = (blockIdx.x * blockDim.x + threadIdx.x) >> 5;
    int lane = threadIdx.x & 31;
    if (warp >= N) return;
    int dst = warp;
    int g = lane >> 3;          // edge slot 0..3
    int l = lane & 7;           // channel block: channels [4l, 4l+4)

    float4 v4 = __ldg((const float4*)&g_v[dst * 32 + l * 4]);
    float4 gv = *(const float4*)&sg[l * 4];
    float4 w0 = __ldg(&((const float4*)&Wm1[192 * 32])[l]);
    float4 w1 = __ldg(&((const float4*)&Wm1[193 * 32])[l]);
    float4 w2 = __ldg(&((const float4*)Wm2)[l]);
    float bm2v = bm2[0];
    float bx = v4.x + gv.x, by = v4.y + gv.y;
    float bz = v4.z + gv.z, bw = v4.w + gv.w;

    int start = g_rowptr[dst], end = g_rowptr[dst + 1];
    for (int idx = start; idx < end; idx += 4) {
        int e = idx + g;
        bool valid = e < end;
        int4 pk = valid ? g_epack[e] : make_int4(0, 0, 0, 0);
        float4 u4 = __ldg((const float4*)&g_u[pk.x * 32 + l * 4]);
        float ax = __int_as_float(pk.z), ay = __int_as_float(pk.w);
        float m0 = u4.x + bx + fmaf(ax, w0.x, ay * w1.x);
        float m1 = u4.y + by + fmaf(ax, w0.y, ay * w1.y);
        float m2 = u4.z + bz + fmaf(ax, w0.z, ay * w1.z);
        float m3 = u4.w + bw + fmaf(ax, w0.w, ay * w1.w);
        m0 = fmaxf(m0, 0.f); m1 = fmaxf(m1, 0.f);
        m2 = fmaxf(m2, 0.f); m3 = fmaxf(m3, 0.f);
        float s = fmaf(m0, w2.x, fmaf(m1, w2.y, fmaf(m2, w2.z, m3 * w2.w)));
        s += __shfl_xor_sync(0xffffffffu, s, 4);
        s += __shfl_xor_sync(0xffffffffu, s, 2);
        s += __shfl_xor_sync(0xffffffffu, s, 1);
        if (valid && l == 0) out[pk.y] = s + bm2v;
    }
}

// ============================================================
extern "C" void kernel_launch(void* const* d_in, const int* in_sizes, int n_in,
                              void* d_out, int out_size) {
    const float* x     = (const float*)d_in[0];
    const int*   ei    = (const int*)d_in[1];
    const float* ea    = (const float*)d_in[2];
    const int*   dest  = (const int*)d_in[3];
    const float* W0    = (const float*)d_in[4];
    const float* b0    = (const float*)d_in[5];
    const float* We0   = (const float*)d_in[6];
    const float* att0  = (const float*)d_in[7];
    const float* bias0 = (const float*)d_in[8];
    const float* W1    = (const float*)d_in[9];
    const float* b1    = (const float*)d_in[10];
    const float* We1   = (const float*)d_in[11];
    const float* att1  = (const float*)d_in[12];
    const float* bias1 = (const float*)d_in[13];
    const float* Wm1   = (const float*)d_in[14];
    const float* bm1   = (const float*)d_in[15];
    const float* Wm2   = (const float*)d_in[16];
    const float* bm2   = (const float*)d_in[17];

    int N = in_sizes[0] / 2;
    int E = in_sizes[1] / 2;

    const int TB = 256;
    int gN   = (N + TB - 1) / TB;
    int gE   = (E + TB - 1) / TB;
    int gN64 = (N * 64 + TB - 1) / TB;
    int gAgg = (N * 32 + TB - 1) / TB;
    int nSB  = (N + 255) / 256;
    int gInit = (gN > 1) ? gN : 1;

    k_init<<<gInit, TB>>>(N);                                           // 0
    k_easum_hist<<<512, TB>>>(ei, (const float2*)ea, E);                // 1
    k_scan<<<nSB, 256>>>(N, E);                                         // 2
    k_scatter_z0<<<gE + gN64, TB>>>(ei, (const float2*)ea, x,
                                    W0, b0, N, E, gE);                  // 3
    k_agg0<<<gAgg, TB>>>(We0, att0, bias0, W1, b1, N);                  // 4
    k_agg1<<<gAgg, TB>>>(We1, att1, bias1, Wm1, dest, N);               // 5
    k_edge<<<gAgg, TB>>>(Wm1, bm1, Wm2, bm2, (float*)d_out, N);         // 6
}

// round 7
// speedup vs baseline: 1.2213x; 1.1067x over previous
#include <cuda_runtime.h>
#include <math.h>

// Problem max sizes (N=50000, E=800000)
#define NMAX 50000
#define EMAX 800000

// ---- static device scratch ----
__device__ float  g_z[NMAX * 64];      // z of current layer (z0, then z1)
__device__ float  g_h[NMAX * 64];      // h of current layer
__device__ float  g_uv[NMAX * 64];     // [u | v] per node
__device__ __align__(16) float g_hdest[64];
__device__ double g_easum[2];
__device__ float  g_eamean[2];
// CSR by dst: packed edge payload {src, perm, ea.x(bits), ea.y(bits)}
__device__ int    g_cnt[NMAX];
__device__ int    g_rowptr[NMAX + 1];
__device__ int    g_rowcur[NMAX];
__device__ int4   g_epack[EMAX];
// decoupled-lookback scan state
__device__ unsigned long long g_tile[256];
__device__ int    g_tilectr;

// ---- packed fp32x2 helpers (Blackwell FFMA2) ----
__device__ __forceinline__ unsigned long long pack2(float a, float b) {
    unsigned long long r;
    asm("mov.b64 %0, {%1, %2};" : "=l"(r) : "f"(a), "f"(b));
    return r;
}
__device__ __forceinline__ unsigned long long fma2(unsigned long long a,
                                                   unsigned long long b,
                                                   unsigned long long c) {
    unsigned long long d;
    asm("fma.rn.f32x2 %0, %1, %2, %3;" : "=l"(d) : "l"(a), "l"(b), "l"(c));
    return d;
}
__device__ __forceinline__ unsigned long long add2(unsigned long long a,
                                                   unsigned long long b) {
    unsigned long long d;
    asm("add.rn.f32x2 %0, %1, %2;" : "=l"(d) : "l"(a), "l"(b));
    return d;
}

// ============================================================
// 0) init
// ============================================================
__global__ void k_init(int N) {
    int i = blockIdx.x * blockDim.x + threadIdx.x;
    if (i < N) g_cnt[i] = 0;
    if (i < 256) g_tile[i] = 0ull;
    if (i == 0) { g_tilectr = 0; g_easum[0] = 0.0; g_easum[1] = 0.0; }
}

// ============================================================
// 1) fused: edge_attr column sums (double) + dst histogram
// ============================================================
__global__ void k_easum_hist(const int* __restrict__ ei,
                             const float2* __restrict__ ea, int E) {
    double d0 = 0.0, d1 = 0.0;
    for (int i = blockIdx.x * blockDim.x + threadIdx.x; i < E;
         i += gridDim.x * blockDim.x) {
        float2 v = ea[i];
        d0 += (double)v.x; d1 += (double)v.y;
        atomicAdd(&g_cnt[ei[E + i]], 1);
    }
    __shared__ double sh0[256], sh1[256];
    int t = threadIdx.x;
    sh0[t] = d0; sh1[t] = d1;
    __syncthreads();
    for (int ofs = 128; ofs > 0; ofs >>= 1) {
        if (t < ofs) { sh0[t] += sh0[t + ofs]; sh1[t] += sh1[t + ofs]; }
        __syncthreads();
    }
    if (t == 0) { atomicAdd(&g_easum[0], sh0[0]); atomicAdd(&g_easum[1], sh1[0]); }
}

// ============================================================
// 2) exclusive scan of g_cnt (decoupled lookback) + eamean
// ============================================================
__global__ void __launch_bounds__(256) k_scan(int N, int E) {
    __shared__ int sbid;
    __shared__ int swsum[8];
    __shared__ int sexcl;
    if (threadIdx.x == 0) sbid = atomicAdd(&g_tilectr, 1);
    __syncthreads();
    int bid = sbid;
    if (bid == 0 && threadIdx.x < 2)
        g_eamean[threadIdx.x] = (float)(g_easum[threadIdx.x] / (double)E);

    int i = bid * 256 + threadIdx.x;
    int v = (i < N) ? g_cnt[i] : 0;
    int lane = threadIdx.x & 31, w = threadIdx.x >> 5;
    int s = v;
#pragma unroll
    for (int o = 1; o < 32; o <<= 1) {
        int t = __shfl_up_sync(0xffffffffu, s, o);
        if (lane >= o) s += t;
    }
    if (lane == 31) swsum[w] = s;
    __syncthreads();
    if (w == 0) {
        int ws = (lane < 8) ? swsum[lane] : 0;
#pragma unroll
        for (int o = 1; o < 8; o <<= 1) {
            int t = __shfl_up_sync(0xffffffffu, ws, o);
            if (lane >= o) ws += t;
        }
        if (lane < 8) swsum[lane] = ws;
    }
    __syncthreads();
    int incl = s + (w > 0 ? swsum[w - 1] : 0);
    int btotal = swsum[7];

    if (threadIdx.x == 0) {
        unsigned long long word = (bid == 0)
            ? ((2ull << 32) | (unsigned)btotal)
            : ((1ull << 32) | (unsigned)btotal);
        atomicExch(&g_tile[bid], word);
    }

    if (bid > 0 && w == 0) {
        int excl = 0;
        int look = bid - 1 - lane;
        for (;;) {
            unsigned long long word = (look >= 0)
                ? atomicAdd(&g_tile[look], 0ull) : (2ull << 32);
            unsigned st = (unsigned)(word >> 32);
            unsigned pend = __ballot_sync(0xffffffffu, st == 0u);
            if (pend) continue;
            unsigned pre = __ballot_sync(0xffffffffu, st == 2u);
            int fp = __ffs(pre) - 1;
            int val = (int)(word & 0xffffffffu);
            if (fp >= 0) {
                int contrib = (lane <= fp && look >= 0) ? val : 0;
#pragma unroll
                for (int o = 16; o > 0; o >>= 1)
                    contrib += __shfl_xor_sync(0xffffffffu, contrib, o);
                excl += contrib;
                break;
            } else {
                int contrib = (look >= 0) ? val : 0;
#pragma unroll
                for (int o = 16; o > 0; o >>= 1)
                    contrib += __shfl_xor_sync(0xffffffffu, contrib, o);
                excl += contrib;
                look -= 32;
            }
        }
        if (lane == 0) {
            atomicExch(&g_tile[bid], (2ull << 32) | (unsigned)(excl + btotal));
            sexcl = excl;
        }
    } else if (threadIdx.x == 0) {
        sexcl = 0;
    }
    __syncthreads();
    int excl = sexcl;
    if (i < N) {
        int ip = excl + incl;
        g_rowptr[i + 1] = ip;
        g_rowcur[i] = ip - v;
    }
    if (i == 0) g_rowptr[0] = 0;
}

// ============================================================
// 3) fused: packed CSR scatter + z0 = x@W0+b0
// ============================================================
__global__ void k_scatter_z0(const int* __restrict__ ei,
                             const float2* __restrict__ ea,
                             const float* __restrict__ x,
                             const float* __restrict__ W0,
                             const float* __restrict__ b0,
                             int N, int E, int gE) {
    if ((int)blockIdx.x < gE) {
        int e = blockIdx.x * 256 + threadIdx.x;
        if (e < E) {
            int dst = ei[E + e];
            int pos = atomicAdd(&g_rowcur[dst], 1);
            float2 a = ea[e];
            g_epack[pos] = make_int4(ei[e], e, __float_as_int(a.x),
                                     __float_as_int(a.y));
        }
    } else {
        int i = (blockIdx.x - gE) * 256 + threadIdx.x;
        if (i < N * 64) {
            int n = i >> 6, j = i & 63;
            g_z[i] = fmaf(x[2 * n], W0[j], fmaf(x[2 * n + 1], W0[64 + j], b0[j]));
        }
    }
}

// ============================================================
// 4/6) GATv2 online-softmax aggregation (pure; no epilogue).
// Warp per dst node; lane handles channels c=2l,2l+1; heads split
// at lane 16. Unrolled by 2 edges. Reads g_z, writes g_h.
// ============================================================
__global__ void __launch_bounds__(256)
k_agg(const float* __restrict__ We, const float* __restrict__ att,
      const float* __restrict__ bias, const int* __restrict__ destp, int N) {
    int dst = (blockIdx.x * blockDim.x + threadIdx.x) >> 5;
    int lane = threadIdx.x & 31;
    if (dst >= N) return;
    int c = lane * 2;

    float We0a = We[c],      We0b = We[c + 1];
    float We1a = We[64 + c], We1b = We[64 + c + 1];
    float at0 = att[c], at1 = att[c + 1];
    float2 zd = __ldg((const float2*)&g_z[dst * 64 + c]);

    // self loop (src=dst, ea=mean)
    float eax = g_eamean[0], eay = g_eamean[1];
    float s0 = zd.x + zd.x + fmaf(eax, We0a, eay * We1a);
    float s1 = zd.y + zd.y + fmaf(eax, We0b, eay * We1b);
    s0 = (s0 > 0.f) ? s0 : 0.2f * s0;
    s1 = (s1 > 0.f) ? s1 : 0.2f * s1;
    float p = fmaf(s0, at0, s1 * at1);
#pragma unroll
    for (int o = 8; o >= 1; o >>= 1) p += __shfl_xor_sync(0xffffffffu, p, o);
    float m = p, denom = 1.f, acc0 = zd.x, acc1 = zd.y;

    int idx = g_rowptr[dst], end = g_rowptr[dst + 1];
    for (; idx + 2 <= end; idx += 2) {
        int4 p1 = g_epack[idx];
        int4 p2 = g_epack[idx + 1];
        float2 za = __ldg((const float2*)&g_z[p1.x * 64 + c]);
        float2 zb = __ldg((const float2*)&g_z[p2.x * 64 + c]);
        float eaAx = __int_as_float(p1.z), eaAy = __int_as_float(p1.w);
        float eaBx = __int_as_float(p2.z), eaBy = __int_as_float(p2.w);

        float a0 = zd.x + za.x + fmaf(eaAx, We0a, eaAy * We1a);
        float a1 = zd.y + za.y + fmaf(eaAx, We0b, eaAy * We1b);
        float b0_ = zd.x + zb.x + fmaf(eaBx, We0a, eaBy * We1a);
        float b1_ = zd.y + zb.y + fmaf(eaBx, We0b, eaBy * We1b);
        a0 = (a0 > 0.f) ? a0 : 0.2f * a0;
        a1 = (a1 > 0.f) ? a1 : 0.2f * a1;
        b0_ = (b0_ > 0.f) ? b0_ : 0.2f * b0_;
        b1_ = (b1_ > 0.f) ? b1_ : 0.2f * b1_;
        float pa = fmaf(a0, at0, a1 * at1);
        float pb = fmaf(b0_, at0, b1_ * at1);
#pragma unroll
        for (int o = 8; o >= 1; o >>= 1) {
            pa += __shfl_xor_sync(0xffffffffu, pa, o);
            pb += __shfl_xor_sync(0xffffffffu, pb, o);
        }
        float mn = fmaxf(m, fmaxf(pa, pb));
        float sc = __expf(m - mn);
        float wa = __expf(pa - mn);
        float wb = __expf(pb - mn);
        denom = fmaf(denom, sc, wa + wb);
        acc0 = fmaf(acc0, sc, fmaf(wa, za.x, wb * zb.x));
        acc1 = fmaf(acc1, sc, fmaf(wa, za.y, wb * zb.y));
        m = mn;
    }
    if (idx < end) {
        int4 p1 = g_epack[idx];
        float2 za = __ldg((const float2*)&g_z[p1.x * 64 + c]);
        float eaAx = __int_as_float(p1.z), eaAy = __int_as_float(p1.w);
        float a0 = zd.x + za.x + fmaf(eaAx, We0a, eaAy * We1a);
        float a1 = zd.y + za.y + fmaf(eaAx, We0b, eaAy * We1b);
        a0 = (a0 > 0.f) ? a0 : 0.2f * a0;
        a1 = (a1 > 0.f) ? a1 : 0.2f * a1;
        float pa = fmaf(a0, at0, a1 * at1);
#pragma unroll
        for (int o = 8; o >= 1; o >>= 1) pa += __shfl_xor_sync(0xffffffffu, pa, o);
        float mn = fmaxf(m, pa);
        float sc = __expf(m - mn);
        float wa = __expf(pa - mn);
        denom = fmaf(denom, sc, wa);
        acc0 = fmaf(acc0, sc, wa * za.x);
        acc1 = fmaf(acc1, sc, wa * za.y);
        m = mn;
    }
    float inv = __fdividef(1.f, denom + 1e-16f);
    float o0 = fmaf(acc0, inv, bias[c]);
    float o1 = fmaf(acc1, inv, bias[c + 1]);
    float h0 = (o0 > 0.f) ? o0 : expm1f(o0);
    float h1 = (o1 > 0.f) ? o1 : expm1f(o1);

    *(float2*)&g_h[dst * 64 + c] = make_float2(h0, h1);
    if (destp && dst == destp[0])
        *(float2*)&g_hdest[c] = make_float2(h0, h1);
}

// ============================================================
// 5/7) register-tiled GEMM on device globals:
// mode 0: g_z[N,64]  = g_h[N,64] @ W (64x64 row-major) + bias
// mode 1: g_uv[N,64] = g_h[N,64] @ W' where
//         W'[k][j] = j<32 ? W[k*32+j] : W[(64+k)*32+j-32]   (no bias)
// Block: 128 threads, 64-node tile; thread = 4 nodes x 8 channels.
// Inner loop uses packed fma.rn.f32x2.
// ============================================================
__global__ void __launch_bounds__(128)
k_gemv(const float* __restrict__ W, const float* __restrict__ bias,
       int N, int mode) {
    __shared__ __align__(16) float sW[64 * 64];
    __shared__ __align__(16) float sA[64 * 68];

    for (int idx = threadIdx.x; idx < 4096; idx += 128) {
        int k = idx >> 6, j = idx & 63;
        sW[idx] = (mode == 0) ? W[idx]
                : ((j < 32) ? W[k * 32 + j] : W[(64 + k) * 32 + (j - 32)]);
    }
    int nbase = blockIdx.x * 64;
    for (int idx = threadIdx.x; idx < 64 * 16; idx += 128) {
        int n = idx >> 4, k4 = idx & 15;
        float4 av = (nbase + n < N)
            ? *(const float4*)&g_h[(nbase + n) * 64 + k4 * 4]
            : make_float4(0.f, 0.f, 0.f, 0.f);
        *(float4*)&sA[n * 68 + k4 * 4] = av;
    }
    __syncthreads();

    int cg = threadIdx.x & 7;        // channels cg*8 .. cg*8+7
    int ng = threadIdx.x >> 3;       // nodes ng*4 .. ng*4+3
    __align__(16) unsigned long long acc[4][4];
#pragma unroll
    for (int i = 0; i < 4; i++)
#pragma unroll
        for (int j = 0; j < 4; j++) acc[i][j] = 0ull;

    for (int k4 = 0; k4 < 16; k4++) {
        float4 a4[4];
#pragma unroll
        for (int i = 0; i < 4; i++)
            a4[i] = *(const float4*)&sA[(ng * 4 + i) * 68 + k4 * 4];
#pragma unroll
        for (int kk = 0; kk < 4; kk++) {
            int k = k4 * 4 + kk;
            ulonglong2 wl = *(const ulonglong2*)&sW[k * 64 + cg * 8];
            ulonglong2 wh = *(const ulonglong2*)&sW[k * 64 + cg * 8 + 4];
#pragma unroll
            for (int i = 0; i < 4; i++) {
                float a = (kk == 0) ? a4[i].x : (kk == 1) ? a4[i].y
                        : (kk == 2) ? a4[i].z : a4[i].w;
                unsigned long long aa = pack2(a, a);
                acc[i][0] = fma2(aa, wl.x, acc[i][0]);
                acc[i][1] = fma2(aa, wl.y, acc[i][1]);
                acc[i][2] = fma2(aa, wh.x, acc[i][2]);
                acc[i][3] = fma2(aa, wh.y, acc[i][3]);
            }
        }
    }
    if (mode == 0) {
        ulonglong2 b0 = *(const ulonglong2*)&bias[cg * 8];
        ulonglong2 b1v = *(const ulonglong2*)&bias[cg * 8 + 4];
#pragma unroll
        for (int i = 0; i < 4; i++) {
            acc[i][0] = add2(acc[i][0], b0.x);
            acc[i][1] = add2(acc[i][1], b0.y);
            acc[i][2] = add2(acc[i][2], b1v.x);
            acc[i][3] = add2(acc[i][3], b1v.y);
        }
    }
    float* C = (mode == 0) ? g_z : g_uv;
#pragma unroll
    for (int i = 0; i < 4; i++) {
        int n = nbase + ng * 4 + i;
        if (n < N) {
            *(float4*)&C[n * 64 + cg * 8]     = *(float4*)&acc[i][0];
            *(float4*)&C[n * 64 + cg * 8 + 4] = *(float4*)&acc[i][2];
        }
    }
}

// ============================================================
// 8) edge MLP, warp per dst node, 4 edges x 8 lanes per iteration.
// v[dst] + gvec hoisted; u gathered from g_uv[src].
// ============================================================
__global__ void __launch_bounds__(256)
k_edge(const float* __restrict__ Wm1, const float* __restrict__ bm1,
       const float* __restrict__ Wm2, const float* __restrict__ bm2,
       float* __restrict__ out, int N) {
    __shared__ float sg[32];
    if (threadIdx.x < 32) {
        int j = threadIdx.x;
        float acc = bm1[j];
#pragma unroll
        for (int k = 0; k < 64; k++)
            acc = fmaf(g_hdest[k], Wm1[(128 + k) * 32 + j], acc);
        sg[j] = acc;
    }
    __syncthreads();

    int warp = (blockIdx.x * blockDim.x + threadIdx.x) >> 5;
    int lane = threadIdx.x & 31;
    if (warp >= N) return;
    int dst = warp;
    int g = lane >> 3;          // edge slot 0..3
    int l = lane & 7;           // channel block: channels [4l, 4l+4)

    float4 v4 = __ldg((const float4*)&g_uv[dst * 64 + 32 + l * 4]);
    float4 gv = *(const float4*)&sg[l * 4];
    float4 w0 = __ldg(&((const float4*)&Wm1[192 * 32])[l]);
    float4 w1 = __ldg(&((const float4*)&Wm1[193 * 32])[l]);
    float4 w2 = __ldg(&((const float4*)Wm2)[l]);
    float bm2v = bm2[0];
    float bx = v4.x + gv.x, by = v4.y + gv.y;
    float bz = v4.z + gv.z, bw = v4.w + gv.w;

    int start = g_rowptr[dst], end = g_rowptr[dst + 1];
    for (int idx = start; idx < end; idx += 4) {
        int e = idx + g;
        bool valid = e < end;
        int4 pk = valid ? g_epack[e] : make_int4(0, 0, 0, 0);
        float4 u4 = __ldg((const float4*)&g_uv[pk.x * 64 + l * 4]);
        float ax = __int_as_float(pk.z), ay = __int_as_float(pk.w);
        float m0 = u4.x + bx + fmaf(ax, w0.x, ay * w1.x);
        float m1 = u4.y + by + fmaf(ax, w0.y, ay * w1.y);
        float m2 = u4.z + bz + fmaf(ax, w0.z, ay * w1.z);
        float m3 = u4.w + bw + fmaf(ax, w0.w, ay * w1.w);
        m0 = fmaxf(m0, 0.f); m1 = fmaxf(m1, 0.f);
        m2 = fmaxf(m2, 0.f); m3 = fmaxf(m3, 0.f);
        float s = fmaf(m0, w2.x, fmaf(m1, w2.y, fmaf(m2, w2.z, m3 * w2.w)));
        s += __shfl_xor_sync(0xffffffffu, s, 4);
        s += __shfl_xor_sync(0xffffffffu, s, 2);
        s += __shfl_xor_sync(0xffffffffu, s, 1);
        if (valid && l == 0) out[pk.y] = s + bm2v;
    }
}

// ============================================================
extern "C" void kernel_launch(void* const* d_in, const int* in_sizes, int n_in,
                              void* d_out, int out_size) {
    const float* x     = (const float*)d_in[0];
    const int*   ei    = (const int*)d_in[1];
    const float* ea    = (const float*)d_in[2];
    const int*   dest  = (const int*)d_in[3];
    const float* W0    = (const float*)d_in[4];
    const float* b0    = (const float*)d_in[5];
    const float* We0   = (const float*)d_in[6];
    const float* att0  = (const float*)d_in[7];
    const float* bias0 = (const float*)d_in[8];
    const float* W1    = (const float*)d_in[9];
    const float* b1    = (const float*)d_in[10];
    const float* We1   = (const float*)d_in[11];
    const float* att1  = (const float*)d_in[12];
    const float* bias1 = (const float*)d_in[13];
    const float* Wm1   = (const float*)d_in[14];
    const float* bm1   = (const float*)d_in[15];
    const float* Wm2   = (const float*)d_in[16];
    const float* bm2   = (const float*)d_in[17];

    int N = in_sizes[0] / 2;
    int E = in_sizes[1] / 2;

    const int TB = 256;
    int gN    = (N + TB - 1) / TB;
    int gE    = (E + TB - 1) / TB;
    int gN64  = (N * 64 + TB - 1) / TB;
    int gAgg  = (N * 32 + TB - 1) / TB;
    int gGemv = (N + 63) / 64;
    int nSB   = (N + 255) / 256;
    int gInit = (gN > 1) ? gN : 1;

    k_init<<<gInit, TB>>>(N);                                           // 0
    k_easum_hist<<<512, TB>>>(ei, (const float2*)ea, E);                // 1
    k_scan<<<nSB, 256>>>(N, E);                                         // 2
    k_scatter_z0<<<gE + gN64, TB>>>(ei, (const float2*)ea, x,
                                    W0, b0, N, E, gE);                  // 3
    // layer 0
    k_agg<<<gAgg, TB>>>(We0, att0, bias0, (const int*)0, N);            // 4
    k_gemv<<<gGemv, 128>>>(W1, b1, N, 0);                               // 5
    // layer 1
    k_agg<<<gAgg, TB>>>(We1, att1, bias1, dest, N);                     // 6
    k_gemv<<<gGemv, 128>>>(Wm1, (const float*)0, N, 1);                 // 7
    // edge scoring head
    k_edge<<<gAgg, TB>>>(Wm1, bm1, Wm2, bm2, (float*)d_out, N);         // 8
}

// round 8
// speedup vs baseline: 1.3127x; 1.0748x over previous
#include <cuda_runtime.h>
#include <math.h>

// Problem max sizes (N=50000, E=800000)
#define NMAX 50000
#define EMAX 800000

// ---- static device scratch ----
__device__ float  g_z[NMAX * 64];      // z of current layer (z0, then z1)
__device__ float  g_h[NMAX * 64];      // h of current layer
__device__ float  g_uv[NMAX * 64];     // [u | v] per node
__device__ __align__(16) float g_hdest[64];
__device__ double g_easum[2];
__device__ float  g_eamean[2];
// CSR by dst: packed edge payload {src, perm, ea.x(bits), ea.y(bits)}
__device__ int    g_cnt[NMAX];
__device__ int    g_rowptr[NMAX + 1];
__device__ int    g_rowcur[NMAX];
__device__ int4   g_epack[EMAX];
// decoupled-lookback scan state
__device__ unsigned long long g_tile[256];
__device__ int    g_tilectr;

// ---- packed fp32x2 helpers (Blackwell FFMA2) ----
__device__ __forceinline__ unsigned long long pack2(float a, float b) {
    unsigned long long r;
    asm("mov.b64 %0, {%1, %2};" : "=l"(r) : "f"(a), "f"(b));
    return r;
}
__device__ __forceinline__ unsigned long long fma2(unsigned long long a,
                                                   unsigned long long b,
                                                   unsigned long long c) {
    unsigned long long d;
    asm("fma.rn.f32x2 %0, %1, %2, %3;" : "=l"(d) : "l"(a), "l"(b), "l"(c));
    return d;
}
__device__ __forceinline__ unsigned long long add2(unsigned long long a,
                                                   unsigned long long b) {
    unsigned long long d;
    asm("add.rn.f32x2 %0, %1, %2;" : "=l"(d) : "l"(a), "l"(b));
    return d;
}

// ============================================================
// 0) init
// ============================================================
__global__ void k_init(int N) {
    int i = blockIdx.x * blockDim.x + threadIdx.x;
    if (i < N) g_cnt[i] = 0;
    if (i < 256) g_tile[i] = 0ull;
    if (i == 0) { g_tilectr = 0; g_easum[0] = 0.0; g_easum[1] = 0.0; }
}

// ============================================================
// 1) fused: edge_attr column sums (double) + dst histogram
// ============================================================
__global__ void k_easum_hist(const int* __restrict__ ei,
                             const float2* __restrict__ ea, int E) {
    double d0 = 0.0, d1 = 0.0;
    for (int i = blockIdx.x * blockDim.x + threadIdx.x; i < E;
         i += gridDim.x * blockDim.x) {
        float2 v = ea[i];
        d0 += (double)v.x; d1 += (double)v.y;
        atomicAdd(&g_cnt[ei[E + i]], 1);
    }
    __shared__ double sh0[256], sh1[256];
    int t = threadIdx.x;
    sh0[t] = d0; sh1[t] = d1;
    __syncthreads();
    for (int ofs = 128; ofs > 0; ofs >>= 1) {
        if (t < ofs) { sh0[t] += sh0[t + ofs]; sh1[t] += sh1[t + ofs]; }
        __syncthreads();
    }
    if (t == 0) { atomicAdd(&g_easum[0], sh0[0]); atomicAdd(&g_easum[1], sh1[0]); }
}

// ============================================================
// 2) exclusive scan of g_cnt (decoupled lookback) + eamean
// ============================================================
__global__ void __launch_bounds__(256) k_scan(int N, int E) {
    __shared__ int sbid;
    __shared__ int swsum[8];
    __shared__ int sexcl;
    if (threadIdx.x == 0) sbid = atomicAdd(&g_tilectr, 1);
    __syncthreads();
    int bid = sbid;
    if (bid == 0 && threadIdx.x < 2)
        g_eamean[threadIdx.x] = (float)(g_easum[threadIdx.x] / (double)E);

    int i = bid * 256 + threadIdx.x;
    int v = (i < N) ? g_cnt[i] : 0;
    int lane = threadIdx.x & 31, w = threadIdx.x >> 5;
    int s = v;
#pragma unroll
    for (int o = 1; o < 32; o <<= 1) {
        int t = __shfl_up_sync(0xffffffffu, s, o);
        if (lane >= o) s += t;
    }
    if (lane == 31) swsum[w] = s;
    __syncthreads();
    if (w == 0) {
        int ws = (lane < 8) ? swsum[lane] : 0;
#pragma unroll
        for (int o = 1; o < 8; o <<= 1) {
            int t = __shfl_up_sync(0xffffffffu, ws, o);
            if (lane >= o) ws += t;
        }
        if (lane < 8) swsum[lane] = ws;
    }
    __syncthreads();
    int incl = s + (w > 0 ? swsum[w - 1] : 0);
    int btotal = swsum[7];

    if (threadIdx.x == 0) {
        unsigned long long word = (bid == 0)
            ? ((2ull << 32) | (unsigned)btotal)
            : ((1ull << 32) | (unsigned)btotal);
        atomicExch(&g_tile[bid], word);
    }

    if (bid > 0 && w == 0) {
        int excl = 0;
        int look = bid - 1 - lane;
        for (;;) {
            unsigned long long word = (look >= 0)
                ? atomicAdd(&g_tile[look], 0ull) : (2ull << 32);
            unsigned st = (unsigned)(word >> 32);
            unsigned pend = __ballot_sync(0xffffffffu, st == 0u);
            if (pend) continue;
            unsigned pre = __ballot_sync(0xffffffffu, st == 2u);
            int fp = __ffs(pre) - 1;
            int val = (int)(word & 0xffffffffu);
            if (fp >= 0) {
                int contrib = (lane <= fp && look >= 0) ? val : 0;
#pragma unroll
                for (int o = 16; o > 0; o >>= 1)
                    contrib += __shfl_xor_sync(0xffffffffu, contrib, o);
                excl += contrib;
                break;
            } else {
                int contrib = (look >= 0) ? val : 0;
#pragma unroll
                for (int o = 16; o > 0; o >>= 1)
                    contrib += __shfl_xor_sync(0xffffffffu, contrib, o);
                excl += contrib;
                look -= 32;
            }
        }
        if (lane == 0) {
            atomicExch(&g_tile[bid], (2ull << 32) | (unsigned)(excl + btotal));
            sexcl = excl;
        }
    } else if (threadIdx.x == 0) {
        sexcl = 0;
    }
    __syncthreads();
    int excl = sexcl;
    if (i < N) {
        int ip = excl + incl;
        g_rowptr[i + 1] = ip;
        g_rowcur[i] = ip - v;
    }
    if (i == 0) g_rowptr[0] = 0;
}

// ============================================================
// 3) fused: packed CSR scatter + vectorized z0 = x@W0+b0
// z0 part: thread handles 8 channels of one node (float4 x2).
// ============================================================
__global__ void k_scatter_z0(const int* __restrict__ ei,
                             const float2* __restrict__ ea,
                             const float2* __restrict__ x,
                             const float* __restrict__ W0,
                             const float* __restrict__ b0,
                             int N, int E, int gE) {
    if ((int)blockIdx.x < gE) {
        int e = blockIdx.x * 256 + threadIdx.x;
        if (e < E) {
            int dst = ei[E + e];
            int pos = atomicAdd(&g_rowcur[dst], 1);
            float2 a = ea[e];
            g_epack[pos] = make_int4(ei[e], e, __float_as_int(a.x),
                                     __float_as_int(a.y));
        }
    } else {
        int i = (blockIdx.x - gE) * 256 + threadIdx.x;   // [0, N*8)
        if (i < N * 8) {
            int n = i >> 3, j = (i & 7) * 8;
            float2 xv = x[n];
            float4 w0a = *(const float4*)&W0[j];
            float4 w0b = *(const float4*)&W0[j + 4];
            float4 w1a = *(const float4*)&W0[64 + j];
            float4 w1b = *(const float4*)&W0[64 + j + 4];
            float4 ba  = *(const float4*)&b0[j];
            float4 bb  = *(const float4*)&b0[j + 4];
            float4 r0, r1;
            r0.x = fmaf(xv.x, w0a.x, fmaf(xv.y, w1a.x, ba.x));
            r0.y = fmaf(xv.x, w0a.y, fmaf(xv.y, w1a.y, ba.y));
            r0.z = fmaf(xv.x, w0a.z, fmaf(xv.y, w1a.z, ba.z));
            r0.w = fmaf(xv.x, w0a.w, fmaf(xv.y, w1a.w, ba.w));
            r1.x = fmaf(xv.x, w0b.x, fmaf(xv.y, w1b.x, bb.x));
            r1.y = fmaf(xv.x, w0b.y, fmaf(xv.y, w1b.y, bb.y));
            r1.z = fmaf(xv.x, w0b.z, fmaf(xv.y, w1b.z, bb.z));
            r1.w = fmaf(xv.x, w0b.w, fmaf(xv.y, w1b.w, bb.w));
            *(float4*)&g_z[n * 64 + j]     = r0;
            *(float4*)&g_z[n * 64 + j + 4] = r1;
        }
    }
}

// ============================================================
// 4/6) GATv2 aggregation with FIXED softmax reference (self-loop
// logit) — no loop-carried max/rescale chain. Warp per dst node;
// lane handles channels c=2l,2l+1; heads split at lane 16.
// Unrolled by 4 edges (MLP=4, independent fma accumulation).
// exp(p - p_self) is exact softmax (ratio-invariant); fp32 exp is
// safe for |p - p_self| < 88, far above the data's logit spread.
// ============================================================
__global__ void __launch_bounds__(256)
k_agg(const float* __restrict__ We, const float* __restrict__ att,
      const float* __restrict__ bias, const int* __restrict__ destp, int N) {
    int dst = (blockIdx.x * blockDim.x + threadIdx.x) >> 5;
    int lane = threadIdx.x & 31;
    if (dst >= N) return;
    int c = lane * 2;

    float We0a = We[c],      We0b = We[c + 1];
    float We1a = We[64 + c], We1b = We[64 + c + 1];
    float at0 = att[c], at1 = att[c + 1];
    float2 zd = __ldg((const float2*)&g_z[dst * 64 + c]);

    // self loop logit (fixed softmax reference m)
    float eax = g_eamean[0], eay = g_eamean[1];
    float s0 = zd.x + zd.x + fmaf(eax, We0a, eay * We1a);
    float s1 = zd.y + zd.y + fmaf(eax, We0b, eay * We1b);
    s0 = (s0 > 0.f) ? s0 : 0.2f * s0;
    s1 = (s1 > 0.f) ? s1 : 0.2f * s1;
    float m = fmaf(s0, at0, s1 * at1);
#pragma unroll
    for (int o = 8; o >= 1; o >>= 1) m += __shfl_xor_sync(0xffffffffu, m, o);

    float denom = 1.f, acc0 = zd.x, acc1 = zd.y;

    int idx = g_rowptr[dst], end = g_rowptr[dst + 1];
    for (; idx + 4 <= end; idx += 4) {
        int4 p1 = g_epack[idx];
        int4 p2 = g_epack[idx + 1];
        int4 p3 = g_epack[idx + 2];
        int4 p4 = g_epack[idx + 3];
        float2 z1 = __ldg((const float2*)&g_z[p1.x * 64 + c]);
        float2 z2 = __ldg((const float2*)&g_z[p2.x * 64 + c]);
        float2 z3 = __ldg((const float2*)&g_z[p3.x * 64 + c]);
        float2 z4 = __ldg((const float2*)&g_z[p4.x * 64 + c]);

        float t, pa, pb, pc, pd;
        t = zd.x + z1.x + fmaf(__int_as_float(p1.z), We0a, __int_as_float(p1.w) * We1a);
        t = (t > 0.f) ? t : 0.2f * t; pa = t * at0;
        t = zd.y + z1.y + fmaf(__int_as_float(p1.z), We0b, __int_as_float(p1.w) * We1b);
        t = (t > 0.f) ? t : 0.2f * t; pa = fmaf(t, at1, pa);
        t = zd.x + z2.x + fmaf(__int_as_float(p2.z), We0a, __int_as_float(p2.w) * We1a);
        t = (t > 0.f) ? t : 0.2f * t; pb = t * at0;
        t = zd.y + z2.y + fmaf(__int_as_float(p2.z), We0b, __int_as_float(p2.w) * We1b);
        t = (t > 0.f) ? t : 0.2f * t; pb = fmaf(t, at1, pb);
        t = zd.x + z3.x + fmaf(__int_as_float(p3.z), We0a, __int_as_float(p3.w) * We1a);
        t = (t > 0.f) ? t : 0.2f * t; pc = t * at0;
        t = zd.y + z3.y + fmaf(__int_as_float(p3.z), We0b, __int_as_float(p3.w) * We1b);
        t = (t > 0.f) ? t : 0.2f * t; pc = fmaf(t, at1, pc);
        t = zd.x + z4.x + fmaf(__int_as_float(p4.z), We0a, __int_as_float(p4.w) * We1a);
        t = (t > 0.f) ? t : 0.2f * t; pd = t * at0;
        t = zd.y + z4.y + fmaf(__int_as_float(p4.z), We0b, __int_as_float(p4.w) * We1b);
        t = (t > 0.f) ? t : 0.2f * t; pd = fmaf(t, at1, pd);

#pragma unroll
        for (int o = 8; o >= 1; o >>= 1) {
            pa += __shfl_xor_sync(0xffffffffu, pa, o);
            pb += __shfl_xor_sync(0xffffffffu, pb, o);
            pc += __shfl_xor_sync(0xffffffffu, pc, o);
            pd += __shfl_xor_sync(0xffffffffu, pd, o);
        }
        float wa = __expf(pa - m);
        float wb = __expf(pb - m);
        float wc = __expf(pc - m);
        float wd = __expf(pd - m);
        denom += (wa + wb) + (wc + wd);
        acc0 = fmaf(wa, z1.x, acc0); acc1 = fmaf(wa, z1.y, acc1);
        acc0 = fmaf(wb, z2.x, acc0); acc1 = fmaf(wb, z2.y, acc1);
        acc0 = fmaf(wc, z3.x, acc0); acc1 = fmaf(wc, z3.y, acc1);
        acc0 = fmaf(wd, z4.x, acc0); acc1 = fmaf(wd, z4.y, acc1);
    }
    for (; idx < end; idx++) {
        int4 p1 = g_epack[idx];
        float2 z1 = __ldg((const float2*)&g_z[p1.x * 64 + c]);
        float t, pa;
        t = zd.x + z1.x + fmaf(__int_as_float(p1.z), We0a, __int_as_float(p1.w) * We1a);
        t = (t > 0.f) ? t : 0.2f * t; pa = t * at0;
        t = zd.y + z1.y + fmaf(__int_as_float(p1.z), We0b, __int_as_float(p1.w) * We1b);
        t = (t > 0.f) ? t : 0.2f * t; pa = fmaf(t, at1, pa);
#pragma unroll
        for (int o = 8; o >= 1; o >>= 1) pa += __shfl_xor_sync(0xffffffffu, pa, o);
        float wa = __expf(pa - m);
        denom += wa;
        acc0 = fmaf(wa, z1.x, acc0);
        acc1 = fmaf(wa, z1.y, acc1);
    }
    float inv = __fdividef(1.f, denom + 1e-16f);
    float o0 = fmaf(acc0, inv, bias[c]);
    float o1 = fmaf(acc1, inv, bias[c + 1]);
    float h0 = (o0 > 0.f) ? o0 : expm1f(o0);
    float h1 = (o1 > 0.f) ? o1 : expm1f(o1);

    *(float2*)&g_h[dst * 64 + c] = make_float2(h0, h1);
    if (destp && dst == destp[0])
        *(float2*)&g_hdest[c] = make_float2(h0, h1);
}

// ============================================================
// 5/7) register-tiled GEMM on device globals:
// mode 0: g_z[N,64]  = g_h[N,64] @ W (64x64 row-major) + bias
// mode 1: g_uv[N,64] = g_h[N,64] @ W' where
//         W'[k][j] = j<32 ? W[k*32+j] : W[(64+k)*32+j-32]   (no bias)
// ============================================================
__global__ void __launch_bounds__(128)
k_gemv(const float* __restrict__ W, const float* __restrict__ bias,
       int N, int mode) {
    __shared__ __align__(16) float sW[64 * 64];
    __shared__ __align__(16) float sA[64 * 68];

    for (int idx = threadIdx.x; idx < 4096; idx += 128) {
        int k = idx >> 6, j = idx & 63;
        sW[idx] = (mode == 0) ? W[idx]
                : ((j < 32) ? W[k * 32 + j] : W[(64 + k) * 32 + (j - 32)]);
    }
    int nbase = blockIdx.x * 64;
    for (int idx = threadIdx.x; idx < 64 * 16; idx += 128) {
        int n = idx >> 4, k4 = idx & 15;
        float4 av = (nbase + n < N)
            ? *(const float4*)&g_h[(nbase + n) * 64 + k4 * 4]
            : make_float4(0.f, 0.f, 0.f, 0.f);
        *(float4*)&sA[n * 68 + k4 * 4] = av;
    }
    __syncthreads();

    int cg = threadIdx.x & 7;        // channels cg*8 .. cg*8+7
    int ng = threadIdx.x >> 3;       // nodes ng*4 .. ng*4+3
    __align__(16) unsigned long long acc[4][4];
#pragma unroll
    for (int i = 0; i < 4; i++)
#pragma unroll
        for (int j = 0; j < 4; j++) acc[i][j] = 0ull;

    for (int k4 = 0; k4 < 16; k4++) {
        float4 a4[4];
#pragma unroll
        for (int i = 0; i < 4; i++)
            a4[i] = *(const float4*)&sA[(ng * 4 + i) * 68 + k4 * 4];
#pragma unroll
        for (int kk = 0; kk < 4; kk++) {
            int k = k4 * 4 + kk;
            ulonglong2 wl = *(const ulonglong2*)&sW[k * 64 + cg * 8];
            ulonglong2 wh = *(const ulonglong2*)&sW[k * 64 + cg * 8 + 4];
#pragma unroll
            for (int i = 0; i < 4; i++) {
                float a = (kk == 0) ? a4[i].x : (kk == 1) ? a4[i].y
                        : (kk == 2) ? a4[i].z : a4[i].w;
                unsigned long long aa = pack2(a, a);
                acc[i][0] = fma2(aa, wl.x, acc[i][0]);
                acc[i][1] = fma2(aa, wl.y, acc[i][1]);
                acc[i][2] = fma2(aa, wh.x, acc[i][2]);
                acc[i][3] = fma2(aa, wh.y, acc[i][3]);
            }
        }
    }
    if (mode == 0) {
        ulonglong2 b0 = *(const ulonglong2*)&bias[cg * 8];
        ulonglong2 b1v = *(const ulonglong2*)&bias[cg * 8 + 4];
#pragma unroll
        for (int i = 0; i < 4; i++) {
            acc[i][0] = add2(acc[i][0], b0.x);
            acc[i][1] = add2(acc[i][1], b0.y);
            acc[i][2] = add2(acc[i][2], b1v.x);
            acc[i][3] = add2(acc[i][3], b1v.y);
        }
    }
    float* C = (mode == 0) ? g_z : g_uv;
#pragma unroll
    for (int i = 0; i < 4; i++) {
        int n = nbase + ng * 4 + i;
        if (n < N) {
            *(float4*)&C[n * 64 + cg * 8]     = *(float4*)&acc[i][0];
            *(float4*)&C[n * 64 + cg * 8 + 4] = *(float4*)&acc[i][2];
        }
    }
}

// ============================================================
// 8) edge MLP, warp per dst node, 4 edges x 8 lanes per iteration.
// v[dst] + gvec hoisted; u gathered from g_uv[src].
// ============================================================
__global__ void __launch_bounds__(256)
k_edge(const float* __restrict__ Wm1, const float* __restrict__ bm1,
       const float* __restrict__ Wm2, const float* __restrict__ bm2,
       float* __restrict__ out, int N) {
    __shared__ float sg[32];
    if (threadIdx.x < 32) {
        int j = threadIdx.x;
        float acc = bm1[j];
#pragma unroll
        for (int k = 0; k < 64; k++)
            acc = fmaf(g_hdest[k], Wm1[(128 + k) * 32 + j], acc);
        sg[j] = acc;
    }
    __syncthreads();

    int warp = (blockIdx.x * blockDim.x + threadIdx.x) >> 5;
    int lane = threadIdx.x & 31;
    if (warp >= N) return;
    int dst = warp;
    int g = lane >> 3;          // edge slot 0..3
    int l = lane & 7;           // channel block: channels [4l, 4l+4)

    float4 v4 = __ldg((const float4*)&g_uv[dst * 64 + 32 + l * 4]);
    float4 gv = *(const float4*)&sg[l * 4];
    float4 w0 = __ldg(&((const float4*)&Wm1[192 * 32])[l]);
    float4 w1 = __ldg(&((const float4*)&Wm1[193 * 32])[l]);
    float4 w2 = __ldg(&((const float4*)Wm2)[l]);
    float bm2v = bm2[0];
    float bx = v4.x + gv.x, by = v4.y + gv.y;
    float bz = v4.z + gv.z, bw = v4.w + gv.w;

    int start = g_rowptr[dst], end = g_rowptr[dst + 1];
    for (int idx = start; idx < end; idx += 4) {
        int e = idx + g;
        bool valid = e < end;
        int4 pk = valid ? g_epack[e] : make_int4(0, 0, 0, 0);
        float4 u4 = __ldg((const float4*)&g_uv[pk.x * 64 + l * 4]);
        float ax = __int_as_float(pk.z), ay = __int_as_float(pk.w);
        float m0 = u4.x + bx + fmaf(ax, w0.x, ay * w1.x);
        float m1 = u4.y + by + fmaf(ax, w0.y, ay * w1.y);
        float m2 = u4.z + bz + fmaf(ax, w0.z, ay * w1.z);
        float m3 = u4.w + bw + fmaf(ax, w0.w, ay * w1.w);
        m0 = fmaxf(m0, 0.f); m1 = fmaxf(m1, 0.f);
        m2 = fmaxf(m2, 0.f); m3 = fmaxf(m3, 0.f);
        float s = fmaf(m0, w2.x, fmaf(m1, w2.y, fmaf(m2, w2.z, m3 * w2.w)));
        s += __shfl_xor_sync(0xffffffffu, s, 4);
        s += __shfl_xor_sync(0xffffffffu, s, 2);
        s += __shfl_xor_sync(0xffffffffu, s, 1);
        if (valid && l == 0) out[pk.y] = s + bm2v;
    }
}

// ============================================================
extern "C" void kernel_launch(void* const* d_in, const int* in_sizes, int n_in,
                              void* d_out, int out_size) {
    const float* x     = (const float*)d_in[0];
    const int*   ei    = (const int*)d_in[1];
    const float* ea    = (const float*)d_in[2];
    const int*   dest  = (const int*)d_in[3];
    const float* W0    = (const float*)d_in[4];
    const float* b0    = (const float*)d_in[5];
    const float* We0   = (const float*)d_in[6];
    const float* att0  = (const float*)d_in[7];
    const float* bias0 = (const float*)d_in[8];
    const float* W1    = (const float*)d_in[9];
    const float* b1    = (const float*)d_in[10];
    const float* We1   = (const float*)d_in[11];
    const float* att1  = (const float*)d_in[12];
    const float* bias1 = (const float*)d_in[13];
    const float* Wm1   = (const float*)d_in[14];
    const float* bm1   = (const float*)d_in[15];
    const float* Wm2   = (const float*)d_in[16];
    const float* bm2   = (const float*)d_in[17];

    int N = in_sizes[0] / 2;
    int E = in_sizes[1] / 2;

    const int TB = 256;
    int gN    = (N + TB - 1) / TB;
    int gE    = (E + TB - 1) / TB;
    int gN8   = (N * 8 + TB - 1) / TB;
    int gAgg  = (N * 32 + TB - 1) / TB;
    int gGemv = (N + 63) / 64;
    int nSB   = (N + 255) / 256;
    int gInit = (gN > 1) ? gN : 1;

    k_init<<<gInit, TB>>>(N);                                           // 0
    k_easum_hist<<<512, TB>>>(ei, (const float2*)ea, E);                // 1
    k_scan<<<nSB, 256>>>(N, E);                                         // 2
    k_scatter_z0<<<gE + gN8, TB>>>(ei, (const float2*)ea,
                                   (const float2*)x, W0, b0, N, E, gE); // 3
    // layer 0
    k_agg<<<gAgg, TB>>>(We0, att0, bias0, (const int*)0, N);            // 4
    k_gemv<<<gGemv, 128>>>(W1, b1, N, 0);                               // 5
    // layer 1
    k_agg<<<gAgg, TB>>>(We1, att1, bias1, dest, N);                     // 6
    k_gemv<<<gGemv, 128>>>(Wm1, (const float*)0, N, 1);                 // 7
    // edge scoring head
    k_edge<<<gAgg, TB>>>(Wm1, bm1, Wm2, bm2, (float*)d_out, N);         // 8
}

// round 9
// speedup vs baseline: 1.3247x; 1.0092x over previous
#include <cuda_runtime.h>
#include <math.h>

// Problem max sizes (N=50000, E=800000)
#define NMAX 50000
#define EMAX 800000

// ---- static device scratch ----
__device__ float  g_z[NMAX * 64];      // z of current layer (z0, then z1)
__device__ float  g_h[NMAX * 64];      // h of current layer
__device__ float  g_uv[NMAX * 64];     // [u | v] per node
__device__ __align__(16) float g_hdest[64];
__device__ double g_easum[2];
__device__ float  g_eamean[2];
// CSR by dst: packed edge payload {src, perm, ea.x(bits), ea.y(bits)}
__device__ int    g_cnt[NMAX];
__device__ int    g_rowptr[NMAX + 1];
__device__ int    g_rowcur[NMAX];
__device__ int4   g_epack[EMAX];
// decoupled-lookback scan state
__device__ unsigned long long g_tile[256];
__device__ int    g_tilectr;

// ---- packed fp32x2 helpers (Blackwell FFMA2) ----
__device__ __forceinline__ unsigned long long pack2(float a, float b) {
    unsigned long long r;
    asm("mov.b64 %0, {%1, %2};" : "=l"(r) : "f"(a), "f"(b));
    return r;
}
__device__ __forceinline__ unsigned long long fma2(unsigned long long a,
                                                   unsigned long long b,
                                                   unsigned long long c) {
    unsigned long long d;
    asm("fma.rn.f32x2 %0, %1, %2, %3;" : "=l"(d) : "l"(a), "l"(b), "l"(c));
    return d;
}
__device__ __forceinline__ unsigned long long add2(unsigned long long a,
                                                   unsigned long long b) {
    unsigned long long d;
    asm("add.rn.f32x2 %0, %1, %2;" : "=l"(d) : "l"(a), "l"(b));
    return d;
}

// ============================================================
// 0) init
// ============================================================
__global__ void k_init(int N) {
    int i = blockIdx.x * blockDim.x + threadIdx.x;
    if (i < N) g_cnt[i] = 0;
    if (i < 256) g_tile[i] = 0ull;
    if (i == 0) { g_tilectr = 0; g_easum[0] = 0.0; g_easum[1] = 0.0; }
}

// ============================================================
// 1) fused: edge_attr column sums (double) + dst histogram
// ============================================================
__global__ void k_easum_hist(const int* __restrict__ ei,
                             const float2* __restrict__ ea, int E) {
    double d0 = 0.0, d1 = 0.0;
    for (int i = blockIdx.x * blockDim.x + threadIdx.x; i < E;
         i += gridDim.x * blockDim.x) {
        float2 v = ea[i];
        d0 += (double)v.x; d1 += (double)v.y;
        atomicAdd(&g_cnt[ei[E + i]], 1);
    }
    __shared__ double sh0[256], sh1[256];
    int t = threadIdx.x;
    sh0[t] = d0; sh1[t] = d1;
    __syncthreads();
    for (int ofs = 128; ofs > 0; ofs >>= 1) {
        if (t < ofs) { sh0[t] += sh0[t + ofs]; sh1[t] += sh1[t + ofs]; }
        __syncthreads();
    }
    if (t == 0) { atomicAdd(&g_easum[0], sh0[0]); atomicAdd(&g_easum[1], sh1[0]); }
}

// ============================================================
// 2) exclusive scan of g_cnt (decoupled lookback) + eamean
// ============================================================
__global__ void __launch_bounds__(256) k_scan(int N, int E) {
    __shared__ int sbid;
    __shared__ int swsum[8];
    __shared__ int sexcl;
    if (threadIdx.x == 0) sbid = atomicAdd(&g_tilectr, 1);
    __syncthreads();
    int bid = sbid;
    if (bid == 0 && threadIdx.x < 2)
        g_eamean[threadIdx.x] = (float)(g_easum[threadIdx.x] / (double)E);

    int i = bid * 256 + threadIdx.x;
    int v = (i < N) ? g_cnt[i] : 0;
    int lane = threadIdx.x & 31, w = threadIdx.x >> 5;
    int s = v;
#pragma unroll
    for (int o = 1; o < 32; o <<= 1) {
        int t = __shfl_up_sync(0xffffffffu, s, o);
        if (lane >= o) s += t;
    }
    if (lane == 31) swsum[w] = s;
    __syncthreads();
    if (w == 0) {
        int ws = (lane < 8) ? swsum[lane] : 0;
#pragma unroll
        for (int o = 1; o < 8; o <<= 1) {
            int t = __shfl_up_sync(0xffffffffu, ws, o);
            if (lane >= o) ws += t;
        }
        if (lane < 8) swsum[lane] = ws;
    }
    __syncthreads();
    int incl = s + (w > 0 ? swsum[w - 1] : 0);
    int btotal = swsum[7];

    if (threadIdx.x == 0) {
        unsigned long long word = (bid == 0)
            ? ((2ull << 32) | (unsigned)btotal)
            : ((1ull << 32) | (unsigned)btotal);
        atomicExch(&g_tile[bid], word);
    }

    if (bid > 0 && w == 0) {
        int excl = 0;
        int look = bid - 1 - lane;
        for (;;) {
            unsigned long long word = (look >= 0)
                ? atomicAdd(&g_tile[look], 0ull) : (2ull << 32);
            unsigned st = (unsigned)(word >> 32);
            unsigned pend = __ballot_sync(0xffffffffu, st == 0u);
            if (pend) continue;
            unsigned pre = __ballot_sync(0xffffffffu, st == 2u);
            int fp = __ffs(pre) - 1;
            int val = (int)(word & 0xffffffffu);
            if (fp >= 0) {
                int contrib = (lane <= fp && look >= 0) ? val : 0;
#pragma unroll
                for (int o = 16; o > 0; o >>= 1)
                    contrib += __shfl_xor_sync(0xffffffffu, contrib, o);
                excl += contrib;
                break;
            } else {
                int contrib = (look >= 0) ? val : 0;
#pragma unroll
                for (int o = 16; o > 0; o >>= 1)
                    contrib += __shfl_xor_sync(0xffffffffu, contrib, o);
                excl += contrib;
                look -= 32;
            }
        }
        if (lane == 0) {
            atomicExch(&g_tile[bid], (2ull << 32) | (unsigned)(excl + btotal));
            sexcl = excl;
        }
    } else if (threadIdx.x == 0) {
        sexcl = 0;
    }
    __syncthreads();
    int excl = sexcl;
    if (i < N) {
        int ip = excl + incl;
        g_rowptr[i + 1] = ip;
        g_rowcur[i] = ip - v;
    }
    if (i == 0) g_rowptr[0] = 0;
}

// ============================================================
// 3) fused: packed CSR scatter + vectorized z0 = x@W0+b0
// ============================================================
__global__ void k_scatter_z0(const int* __restrict__ ei,
                             const float2* __restrict__ ea,
                             const float2* __restrict__ x,
                             const float* __restrict__ W0,
                             const float* __restrict__ b0,
                             int N, int E, int gE) {
    if ((int)blockIdx.x < gE) {
        int e = blockIdx.x * 256 + threadIdx.x;
        if (e < E) {
            int dst = ei[E + e];
            int pos = atomicAdd(&g_rowcur[dst], 1);
            float2 a = ea[e];
            g_epack[pos] = make_int4(ei[e], e, __float_as_int(a.x),
                                     __float_as_int(a.y));
        }
    } else {
        int i = (blockIdx.x - gE) * 256 + threadIdx.x;   // [0, N*8)
        if (i < N * 8) {
            int n = i >> 3, j = (i & 7) * 8;
            float2 xv = x[n];
            float4 w0a = *(const float4*)&W0[j];
            float4 w0b = *(const float4*)&W0[j + 4];
            float4 w1a = *(const float4*)&W0[64 + j];
            float4 w1b = *(const float4*)&W0[64 + j + 4];
            float4 ba  = *(const float4*)&b0[j];
            float4 bb  = *(const float4*)&b0[j + 4];
            float4 r0, r1;
            r0.x = fmaf(xv.x, w0a.x, fmaf(xv.y, w1a.x, ba.x));
            r0.y = fmaf(xv.x, w0a.y, fmaf(xv.y, w1a.y, ba.y));
            r0.z = fmaf(xv.x, w0a.z, fmaf(xv.y, w1a.z, ba.z));
            r0.w = fmaf(xv.x, w0a.w, fmaf(xv.y, w1a.w, ba.w));
            r1.x = fmaf(xv.x, w0b.x, fmaf(xv.y, w1b.x, bb.x));
            r1.y = fmaf(xv.x, w0b.y, fmaf(xv.y, w1b.y, bb.y));
            r1.z = fmaf(xv.x, w0b.z, fmaf(xv.y, w1b.z, bb.z));
            r1.w = fmaf(xv.x, w0b.w, fmaf(xv.y, w1b.w, bb.w));
            *(float4*)&g_z[n * 64 + j]     = r0;
            *(float4*)&g_z[n * 64 + j + 4] = r1;
        }
    }
}

// ============================================================
// 4/6) GATv2 aggregation, fixed softmax reference (self-loop
// logit) + half-warp edge parallelism.
// Warp = dst node. lane = half*16 + q; q handles channels
// 4q..4q+3 (float4). Heads occupy 8-lane groups, so the logit
// reduce (xor 4,2,1) is SHARED by both half-warps: half 0
// processes even edge positions, half 1 odd. With the shared
// fixed reference, partial {denom, acc} merge by plain addition
// (5 xor-16 shuffles at the end). Unrolled x2 (4 edges in flight).
// ============================================================
__global__ void __launch_bounds__(256)
k_agg(const float* __restrict__ We, const float* __restrict__ att,
      const float* __restrict__ bias, const int* __restrict__ destp, int N) {
    int dst = (blockIdx.x * blockDim.x + threadIdx.x) >> 5;
    int lane = threadIdx.x & 31;
    if (dst >= N) return;
    int half = lane >> 4;
    int q = lane & 15;
    int ch = q * 4;

    float4 We0 = *(const float4*)&We[ch];
    float4 We1 = *(const float4*)&We[64 + ch];
    float4 at  = *(const float4*)&att[ch];
    float4 zd  = __ldg((const float4*)&g_z[dst * 64 + ch]);

    // self-loop logit = fixed softmax reference m
    float eax = g_eamean[0], eay = g_eamean[1];
    float t, m;
    t = zd.x + zd.x + fmaf(eax, We0.x, eay * We1.x);
    t = (t > 0.f) ? t : 0.2f * t; m = t * at.x;
    t = zd.y + zd.y + fmaf(eax, We0.y, eay * We1.y);
    t = (t > 0.f) ? t : 0.2f * t; m = fmaf(t, at.y, m);
    t = zd.z + zd.z + fmaf(eax, We0.z, eay * We1.z);
    t = (t > 0.f) ? t : 0.2f * t; m = fmaf(t, at.z, m);
    t = zd.w + zd.w + fmaf(eax, We0.w, eay * We1.w);
    t = (t > 0.f) ? t : 0.2f * t; m = fmaf(t, at.w, m);
#pragma unroll
    for (int o = 4; o >= 1; o >>= 1) m += __shfl_xor_sync(0xffffffffu, m, o);

    // self-loop contribution counted once (half 0 only)
    float denom = (half == 0) ? 1.f : 0.f;
    float4 acc;
    acc.x = (half == 0) ? zd.x : 0.f;
    acc.y = (half == 0) ? zd.y : 0.f;
    acc.z = (half == 0) ? zd.z : 0.f;
    acc.w = (half == 0) ? zd.w : 0.f;

    int idx = g_rowptr[dst], end = g_rowptr[dst + 1];
    // main loop: 4 edges per iteration (2 per half-warp)
    for (; idx + 4 <= end; idx += 4) {
        int4 pA = g_epack[idx + half];
        int4 pB = g_epack[idx + 2 + half];
        float4 zA = __ldg((const float4*)&g_z[pA.x * 64 + ch]);
        float4 zB = __ldg((const float4*)&g_z[pB.x * 64 + ch]);
        float eAx = __int_as_float(pA.z), eAy = __int_as_float(pA.w);
        float eBx = __int_as_float(pB.z), eBy = __int_as_float(pB.w);

        float pa, pb;
        t = zd.x + zA.x + fmaf(eAx, We0.x, eAy * We1.x);
        t = (t > 0.f) ? t : 0.2f * t; pa = t * at.x;
        t = zd.y + zA.y + fmaf(eAx, We0.y, eAy * We1.y);
        t = (t > 0.f) ? t : 0.2f * t; pa = fmaf(t, at.y, pa);
        t = zd.z + zA.z + fmaf(eAx, We0.z, eAy * We1.z);
        t = (t > 0.f) ? t : 0.2f * t; pa = fmaf(t, at.z, pa);
        t = zd.w + zA.w + fmaf(eAx, We0.w, eAy * We1.w);
        t = (t > 0.f) ? t : 0.2f * t; pa = fmaf(t, at.w, pa);

        t = zd.x + zB.x + fmaf(eBx, We0.x, eBy * We1.x);
        t = (t > 0.f) ? t : 0.2f * t; pb = t * at.x;
        t = zd.y + zB.y + fmaf(eBx, We0.y, eBy * We1.y);
        t = (t > 0.f) ? t : 0.2f * t; pb = fmaf(t, at.y, pb);
        t = zd.z + zB.z + fmaf(eBx, We0.z, eBy * We1.z);
        t = (t > 0.f) ? t : 0.2f * t; pb = fmaf(t, at.z, pb);
        t = zd.w + zB.w + fmaf(eBx, We0.w, eBy * We1.w);
        t = (t > 0.f) ? t : 0.2f * t; pb = fmaf(t, at.w, pb);

        // shared reduce: both half-warps' edges reduced by the same shuffles
#pragma unroll
        for (int o = 4; o >= 1; o >>= 1) {
            pa += __shfl_xor_sync(0xffffffffu, pa, o);
            pb += __shfl_xor_sync(0xffffffffu, pb, o);
        }
        float wa = __expf(pa - m);
        float wb = __expf(pb - m);
        denom += wa + wb;
        acc.x = fmaf(wa, zA.x, acc.x); acc.x = fmaf(wb, zB.x, acc.x);
        acc.y = fmaf(wa, zA.y, acc.y); acc.y = fmaf(wb, zB.y, acc.y);
        acc.z = fmaf(wa, zA.z, acc.z); acc.z = fmaf(wb, zB.z, acc.z);
        acc.w = fmaf(wa, zA.w, acc.w); acc.w = fmaf(wb, zB.w, acc.w);
    }
    // remainder: up to 3 edges, 2 at a time with validity guard
    for (; idx < end; idx += 2) {
        int e = idx + half;
        bool valid = e < end;
        int4 pA = g_epack[valid ? e : (end - 1)];
        float4 zA = __ldg((const float4*)&g_z[pA.x * 64 + ch]);
        float eAx = __int_as_float(pA.z), eAy = __int_as_float(pA.w);
        float pa;
        t = zd.x + zA.x + fmaf(eAx, We0.x, eAy * We1.x);
        t = (t > 0.f) ? t : 0.2f * t; pa = t * at.x;
        t = zd.y + zA.y + fmaf(eAx, We0.y, eAy * We1.y);
        t = (t > 0.f) ? t : 0.2f * t; pa = fmaf(t, at.y, pa);
        t = zd.z + zA.z + fmaf(eAx, We0.z, eAy * We1.z);
        t = (t > 0.f) ? t : 0.2f * t; pa = fmaf(t, at.z, pa);
        t = zd.w + zA.w + fmaf(eAx, We0.w, eAy * We1.w);
        t = (t > 0.f) ? t : 0.2f * t; pa = fmaf(t, at.w, pa);
#pragma unroll
        for (int o = 4; o >= 1; o >>= 1) pa += __shfl_xor_sync(0xffffffffu, pa, o);
        float wa = valid ? __expf(pa - m) : 0.f;
        denom += wa;
        acc.x = fmaf(wa, zA.x, acc.x);
        acc.y = fmaf(wa, zA.y, acc.y);
        acc.z = fmaf(wa, zA.z, acc.z);
        acc.w = fmaf(wa, zA.w, acc.w);
    }
    // merge half-warps (shared m -> plain addition)
    denom += __shfl_xor_sync(0xffffffffu, denom, 16);
    acc.x += __shfl_xor_sync(0xffffffffu, acc.x, 16);
    acc.y += __shfl_xor_sync(0xffffffffu, acc.y, 16);
    acc.z += __shfl_xor_sync(0xffffffffu, acc.z, 16);
    acc.w += __shfl_xor_sync(0xffffffffu, acc.w, 16);

    if (half == 0) {
        float inv = __fdividef(1.f, denom + 1e-16f);
        float4 b4 = *(const float4*)&bias[ch];
        float o; float4 h;
        o = fmaf(acc.x, inv, b4.x); h.x = (o > 0.f) ? o : expm1f(o);
        o = fmaf(acc.y, inv, b4.y); h.y = (o > 0.f) ? o : expm1f(o);
        o = fmaf(acc.z, inv, b4.z); h.z = (o > 0.f) ? o : expm1f(o);
        o = fmaf(acc.w, inv, b4.w); h.w = (o > 0.f) ? o : expm1f(o);
        *(float4*)&g_h[dst * 64 + ch] = h;
        if (destp && dst == destp[0]) *(float4*)&g_hdest[ch] = h;
    }
}

// ============================================================
// 5/7) register-tiled GEMM on device globals:
// mode 0: g_z[N,64]  = g_h[N,64] @ W (64x64 row-major) + bias
// mode 1: g_uv[N,64] = g_h[N,64] @ W' where
//         W'[k][j] = j<32 ? W[k*32+j] : W[(64+k)*32+j-32]   (no bias)
// ============================================================
__global__ void __launch_bounds__(128)
k_gemv(const float* __restrict__ W, const float* __restrict__ bias,
       int N, int mode) {
    __shared__ __align__(16) float sW[64 * 64];
    __shared__ __align__(16) float sA[64 * 68];

    for (int idx = threadIdx.x; idx < 4096; idx += 128) {
        int k = idx >> 6, j = idx & 63;
        sW[idx] = (mode == 0) ? W[idx]
                : ((j < 32) ? W[k * 32 + j] : W[(64 + k) * 32 + (j - 32)]);
    }
    int nbase = blockIdx.x * 64;
    for (int idx = threadIdx.x; idx < 64 * 16; idx += 128) {
        int n = idx >> 4, k4 = idx & 15;
        float4 av = (nbase + n < N)
            ? *(const float4*)&g_h[(nbase + n) * 64 + k4 * 4]
            : make_float4(0.f, 0.f, 0.f, 0.f);
        *(float4*)&sA[n * 68 + k4 * 4] = av;
    }
    __syncthreads();

    int cg = threadIdx.x & 7;        // channels cg*8 .. cg*8+7
    int ng = threadIdx.x >> 3;       // nodes ng*4 .. ng*4+3
    __align__(16) unsigned long long acc[4][4];
#pragma unroll
    for (int i = 0; i < 4; i++)
#pragma unroll
        for (int j = 0; j < 4; j++) acc[i][j] = 0ull;

    for (int k4 = 0; k4 < 16; k4++) {
        float4 a4[4];
#pragma unroll
        for (int i = 0; i < 4; i++)
            a4[i] = *(const float4*)&sA[(ng * 4 + i) * 68 + k4 * 4];
#pragma unroll
        for (int kk = 0; kk < 4; kk++) {
            int k = k4 * 4 + kk;
            ulonglong2 wl = *(const ulonglong2*)&sW[k * 64 + cg * 8];
            ulonglong2 wh = *(const ulonglong2*)&sW[k * 64 + cg * 8 + 4];
#pragma unroll
            for (int i = 0; i < 4; i++) {
                float a = (kk == 0) ? a4[i].x : (kk == 1) ? a4[i].y
                        : (kk == 2) ? a4[i].z : a4[i].w;
                unsigned long long aa = pack2(a, a);
                acc[i][0] = fma2(aa, wl.x, acc[i][0]);
                acc[i][1] = fma2(aa, wl.y, acc[i][1]);
                acc[i][2] = fma2(aa, wh.x, acc[i][2]);
                acc[i][3] = fma2(aa, wh.y, acc[i][3]);
            }
        }
    }
    if (mode == 0) {
        ulonglong2 b0 = *(const ulonglong2*)&bias[cg * 8];
        ulonglong2 b1v = *(const ulonglong2*)&bias[cg * 8 + 4];
#pragma unroll
        for (int i = 0; i < 4; i++) {
            acc[i][0] = add2(acc[i][0], b0.x);
            acc[i][1] = add2(acc[i][1], b0.y);
            acc[i][2] = add2(acc[i][2], b1v.x);
            acc[i][3] = add2(acc[i][3], b1v.y);
        }
    }
    float* C = (mode == 0) ? g_z : g_uv;
#pragma unroll
    for (int i = 0; i < 4; i++) {
        int n = nbase + ng * 4 + i;
        if (n < N) {
            *(float4*)&C[n * 64 + cg * 8]     = *(float4*)&acc[i][0];
            *(float4*)&C[n * 64 + cg * 8 + 4] = *(float4*)&acc[i][2];
        }
    }
}

// ============================================================
// 8) edge MLP, warp per dst node, 4 edges x 8 lanes per iteration.
// v[dst] + gvec hoisted; u gathered from g_uv[src].
// ============================================================
__global__ void __launch_bounds__(256)
k_edge(const float* __restrict__ Wm1, const float* __restrict__ bm1,
       const float* __restrict__ Wm2, const float* __restrict__ bm2,
       float* __restrict__ out, int N) {
    __shared__ float sg[32];
    if (threadIdx.x < 32) {
        int j = threadIdx.x;
        float acc = bm1[j];
#pragma unroll
        for (int k = 0; k < 64; k++)
            acc = fmaf(g_hdest[k], Wm1[(128 + k) * 32 + j], acc);
        sg[j] = acc;
    }
    __syncthreads();

    int warp = (blockIdx.x * blockDim.x + threadIdx.x) >> 5;
    int lane = threadIdx.x & 31;
    if (warp >= N) return;
    int dst = warp;
    int g = lane >> 3;          // edge slot 0..3
    int l = lane & 7;           // channel block: channels [4l, 4l+4)

    float4 v4 = __ldg((const float4*)&g_uv[dst * 64 + 32 + l * 4]);
    float4 gv = *(const float4*)&sg[l * 4];
    float4 w0 = __ldg(&((const float4*)&Wm1[192 * 32])[l]);
    float4 w1 = __ldg(&((const float4*)&Wm1[193 * 32])[l]);
    float4 w2 = __ldg(&((const float4*)Wm2)[l]);
    float bm2v = bm2[0];
    float bx = v4.x + gv.x, by = v4.y + gv.y;
    float bz = v4.z + gv.z, bw = v4.w + gv.w;

    int start = g_rowptr[dst], end = g_rowptr[dst + 1];
    for (int idx = start; idx < end; idx += 4) {
        int e = idx + g;
        bool valid = e < end;
        int4 pk = valid ? g_epack[e] : make_int4(0, 0, 0, 0);
        float4 u4 = __ldg((const float4*)&g_uv[pk.x * 64 + l * 4]);
        float ax = __int_as_float(pk.z), ay = __int_as_float(pk.w);
        float m0 = u4.x + bx + fmaf(ax, w0.x, ay * w1.x);
        float m1 = u4.y + by + fmaf(ax, w0.y, ay * w1.y);
        float m2 = u4.z + bz + fmaf(ax, w0.z, ay * w1.z);
        float m3 = u4.w + bw + fmaf(ax, w0.w, ay * w1.w);
        m0 = fmaxf(m0, 0.f); m1 = fmaxf(m1, 0.f);
        m2 = fmaxf(m2, 0.f); m3 = fmaxf(m3, 0.f);
        float s = fmaf(m0, w2.x, fmaf(m1, w2.y, fmaf(m2, w2.z, m3 * w2.w)));
        s += __shfl_xor_sync(0xffffffffu, s, 4);
        s += __shfl_xor_sync(0xffffffffu, s, 2);
        s += __shfl_xor_sync(0xffffffffu, s, 1);
        if (valid && l == 0) out[pk.y] = s + bm2v;
    }
}

// ============================================================
extern "C" void kernel_launch(void* const* d_in, const int* in_sizes, int n_in,
                              void* d_out, int out_size) {
    const float* x     = (const float*)d_in[0];
    const int*   ei    = (const int*)d_in[1];
    const float* ea    = (const float*)d_in[2];
    const int*   dest  = (const int*)d_in[3];
    const float* W0    = (const float*)d_in[4];
    const float* b0    = (const float*)d_in[5];
    const float* We0   = (const float*)d_in[6];
    const float* att0  = (const float*)d_in[7];
    const float* bias0 = (const float*)d_in[8];
    const float* W1    = (const float*)d_in[9];
    const float* b1    = (const float*)d_in[10];
    const float* We1   = (const float*)d_in[11];
    const float* att1  = (const float*)d_in[12];
    const float* bias1 = (const float*)d_in[13];
    const float* Wm1   = (const float*)d_in[14];
    const float* bm1   = (const float*)d_in[15];
    const float* Wm2   = (const float*)d_in[16];
    const float* bm2   = (const float*)d_in[17];

    int N = in_sizes[0] / 2;
    int E = in_sizes[1] / 2;

    const int TB = 256;
    int gN    = (N + TB - 1) / TB;
    int gE    = (E + TB - 1) / TB;
    int gN8   = (N * 8 + TB - 1) / TB;
    int gAgg  = (N * 32 + TB - 1) / TB;
    int gGemv = (N + 63) / 64;
    int nSB   = (N + 255) / 256;
    int gInit = (gN > 1) ? gN : 1;

    k_init<<<gInit, TB>>>(N);                                           // 0
    k_easum_hist<<<512, TB>>>(ei, (const float2*)ea, E);                // 1
    k_scan<<<nSB, 256>>>(N, E);                                         // 2
    k_scatter_z0<<<gE + gN8, TB>>>(ei, (const float2*)ea,
                                   (const float2*)x, W0, b0, N, E, gE); // 3
    // layer 0
    k_agg<<<gAgg, TB>>>(We0, att0, bias0, (const int*)0, N);            // 4
    k_gemv<<<gGemv, 128>>>(W1, b1, N, 0);                               // 5
    // layer 1
    k_agg<<<gAgg, TB>>>(We1, att1, bias1, dest, N);                     // 6
    k_gemv<<<gGemv, 128>>>(Wm1, (const float*)0, N, 1);                 // 7
    // edge scoring head
    k_edge<<<gAgg, TB>>>(Wm1, bm1, Wm2, bm2, (float*)d_out, N);         // 8
}

// round 10
// speedup vs baseline: 1.3870x; 1.0470x over previous
#include <cuda_runtime.h>
#include <math.h>

// Problem max sizes (N=50000, E=800000)
#define NMAX 50000
#define EMAX 800000

// ---- static device scratch (zero-initialized at module load; the
// pipeline re-zeroes cnt/tile/tilectr/easum each run in k_scatter_z0) ----
__device__ float  g_z[NMAX * 64];      // z of current layer (z0, then z1)
__device__ float  g_h[NMAX * 64];      // h of current layer
__device__ float  g_uv[NMAX * 64];     // [u | v] per node
__device__ __align__(16) float g_hdest[64];
__device__ double g_easum[2];
__device__ float  g_eamean[2];
// CSR by dst: packed edge payload {src, perm, ea.x(bits), ea.y(bits)}
__device__ int    g_cnt[NMAX];
__device__ int    g_rowptr[NMAX + 1];
__device__ int    g_rowcur[NMAX];
__device__ int4   g_epack[EMAX];
// decoupled-lookback scan state
__device__ unsigned long long g_tile[256];
__device__ int    g_tilectr;

// ---- packed fp32x2 helpers (Blackwell FFMA2) ----
__device__ __forceinline__ unsigned long long pack2(float a, float b) {
    unsigned long long r;
    asm("mov.b64 %0, {%1, %2};" : "=l"(r) : "f"(a), "f"(b));
    return r;
}
__device__ __forceinline__ unsigned long long fma2(unsigned long long a,
                                                   unsigned long long b,
                                                   unsigned long long c) {
    unsigned long long d;
    asm("fma.rn.f32x2 %0, %1, %2, %3;" : "=l"(d) : "l"(a), "l"(b), "l"(c));
    return d;
}
__device__ __forceinline__ unsigned long long add2(unsigned long long a,
                                                   unsigned long long b) {
    unsigned long long d;
    asm("add.rn.f32x2 %0, %1, %2;" : "=l"(d) : "l"(a), "l"(b));
    return d;
}

// ============================================================
// 0) fused: edge_attr column sums (double) + dst histogram
// (g_cnt / g_easum are zero on entry: module-load zero-init on the
//  first call, re-zeroed by k_scatter_z0 on every subsequent run)
// ============================================================
__global__ void k_easum_hist(const int* __restrict__ ei,
                             const float2* __restrict__ ea, int E) {
    double d0 = 0.0, d1 = 0.0;
    for (int i = blockIdx.x * blockDim.x + threadIdx.x; i < E;
         i += gridDim.x * blockDim.x) {
        float2 v = ea[i];
        d0 += (double)v.x; d1 += (double)v.y;
        atomicAdd(&g_cnt[ei[E + i]], 1);
    }
    __shared__ double sh0[256], sh1[256];
    int t = threadIdx.x;
    sh0[t] = d0; sh1[t] = d1;
    __syncthreads();
    for (int ofs = 128; ofs > 0; ofs >>= 1) {
        if (t < ofs) { sh0[t] += sh0[t + ofs]; sh1[t] += sh1[t + ofs]; }
        __syncthreads();
    }
    if (t == 0) { atomicAdd(&g_easum[0], sh0[0]); atomicAdd(&g_easum[1], sh1[0]); }
}

// ============================================================
// 1) exclusive scan of g_cnt (decoupled lookback) + eamean
// ============================================================
__global__ void __launch_bounds__(256) k_scan(int N, int E) {
    __shared__ int sbid;
    __shared__ int swsum[8];
    __shared__ int sexcl;
    if (threadIdx.x == 0) sbid = atomicAdd(&g_tilectr, 1);
    __syncthreads();
    int bid = sbid;
    if (bid == 0 && threadIdx.x < 2)
        g_eamean[threadIdx.x] = (float)(g_easum[threadIdx.x] / (double)E);

    int i = bid * 256 + threadIdx.x;
    int v = (i < N) ? g_cnt[i] : 0;
    int lane = threadIdx.x & 31, w = threadIdx.x >> 5;
    int s = v;
#pragma unroll
    for (int o = 1; o < 32; o <<= 1) {
        int t = __shfl_up_sync(0xffffffffu, s, o);
        if (lane >= o) s += t;
    }
    if (lane == 31) swsum[w] = s;
    __syncthreads();
    if (w == 0) {
        int ws = (lane < 8) ? swsum[lane] : 0;
#pragma unroll
        for (int o = 1; o < 8; o <<= 1) {
            int t = __shfl_up_sync(0xffffffffu, ws, o);
            if (lane >= o) ws += t;
        }
        if (lane < 8) swsum[lane] = ws;
    }
    __syncthreads();
    int incl = s + (w > 0 ? swsum[w - 1] : 0);
    int btotal = swsum[7];

    if (threadIdx.x == 0) {
        unsigned long long word = (bid == 0)
            ? ((2ull << 32) | (unsigned)btotal)
            : ((1ull << 32) | (unsigned)btotal);
        atomicExch(&g_tile[bid], word);
    }

    if (bid > 0 && w == 0) {
        int excl = 0;
        int look = bid - 1 - lane;
        for (;;) {
            unsigned long long word = (look >= 0)
                ? atomicAdd(&g_tile[look], 0ull) : (2ull << 32);
            unsigned st = (unsigned)(word >> 32);
            unsigned pend = __ballot_sync(0xffffffffu, st == 0u);
            if (pend) continue;
            unsigned pre = __ballot_sync(0xffffffffu, st == 2u);
            int fp = __ffs(pre) - 1;
            int val = (int)(word & 0xffffffffu);
            if (fp >= 0) {
                int contrib = (lane <= fp && look >= 0) ? val : 0;
#pragma unroll
                for (int o = 16; o > 0; o >>= 1)
                    contrib += __shfl_xor_sync(0xffffffffu, contrib, o);
                excl += contrib;
                break;
            } else {
                int contrib = (look >= 0) ? val : 0;
#pragma unroll
                for (int o = 16; o > 0; o >>= 1)
                    contrib += __shfl_xor_sync(0xffffffffu, contrib, o);
                excl += contrib;
                look -= 32;
            }
        }
        if (lane == 0) {
            atomicExch(&g_tile[bid], (2ull << 32) | (unsigned)(excl + btotal));
            sexcl = excl;
        }
    } else if (threadIdx.x == 0) {
        sexcl = 0;
    }
    __syncthreads();
    int excl = sexcl;
    if (i < N) {
        int ip = excl + incl;
        g_rowptr[i + 1] = ip;
        g_rowcur[i] = ip - v;
    }
    if (i == 0) g_rowptr[0] = 0;
}

// ============================================================
// 2) fused: packed CSR scatter + vectorized z0 = x@W0+b0
//    + re-zero cnt/tile/tilectr/easum for the next run
// ============================================================
__global__ void k_scatter_z0(const int* __restrict__ ei,
                             const float2* __restrict__ ea,
                             const float2* __restrict__ x,
                             const float* __restrict__ W0,
                             const float* __restrict__ b0,
                             int N, int E, int gE) {
    if ((int)blockIdx.x < gE) {
        int e = blockIdx.x * 256 + threadIdx.x;
        if (e < E) {
            int dst = ei[E + e];
            int pos = atomicAdd(&g_rowcur[dst], 1);
            float2 a = ea[e];
            g_epack[pos] = make_int4(ei[e], e, __float_as_int(a.x),
                                     __float_as_int(a.y));
        }
    } else {
        int i = (blockIdx.x - gE) * 256 + threadIdx.x;   // [0, N*8)
        // re-zero scan/hist state (last readers already ran)
        if (i < N) g_cnt[i] = 0;
        if (i < 256) g_tile[i] = 0ull;
        if (i == 0) { g_tilectr = 0; g_easum[0] = 0.0; g_easum[1] = 0.0; }
        if (i < N * 8) {
            int n = i >> 3, j = (i & 7) * 8;
            float2 xv = x[n];
            float4 w0a = *(const float4*)&W0[j];
            float4 w0b = *(const float4*)&W0[j + 4];
            float4 w1a = *(const float4*)&W0[64 + j];
            float4 w1b = *(const float4*)&W0[64 + j + 4];
            float4 ba  = *(const float4*)&b0[j];
            float4 bb  = *(const float4*)&b0[j + 4];
            float4 r0, r1;
            r0.x = fmaf(xv.x, w0a.x, fmaf(xv.y, w1a.x, ba.x));
            r0.y = fmaf(xv.x, w0a.y, fmaf(xv.y, w1a.y, ba.y));
            r0.z = fmaf(xv.x, w0a.z, fmaf(xv.y, w1a.z, ba.z));
            r0.w = fmaf(xv.x, w0a.w, fmaf(xv.y, w1a.w, ba.w));
            r1.x = fmaf(xv.x, w0b.x, fmaf(xv.y, w1b.x, bb.x));
            r1.y = fmaf(xv.x, w0b.y, fmaf(xv.y, w1b.y, bb.y));
            r1.z = fmaf(xv.x, w0b.z, fmaf(xv.y, w1b.z, bb.z));
            r1.w = fmaf(xv.x, w0b.w, fmaf(xv.y, w1b.w, bb.w));
            *(float4*)&g_z[n * 64 + j]     = r0;
            *(float4*)&g_z[n * 64 + j + 4] = r1;
        }
    }
}

// ============================================================
// 3/5) GATv2 aggregation, fixed softmax reference + half-warp
// edge parallelism + SOFTWARE-PIPELINED epack prefetch (breaks the
// epack->z two-level L2 dependency chain).
// ============================================================
__global__ void __launch_bounds__(256)
k_agg(const float* __restrict__ We, const float* __restrict__ att,
      const float* __restrict__ bias, const int* __restrict__ destp, int N) {
    int dst = (blockIdx.x * blockDim.x + threadIdx.x) >> 5;
    int lane = threadIdx.x & 31;
    if (dst >= N) return;
    int half = lane >> 4;
    int q = lane & 15;
    int ch = q * 4;

    float4 We0 = *(const float4*)&We[ch];
    float4 We1 = *(const float4*)&We[64 + ch];
    float4 at  = *(const float4*)&att[ch];
    float4 zd  = __ldg((const float4*)&g_z[dst * 64 + ch]);

    // self-loop logit = fixed softmax reference m
    float eax = g_eamean[0], eay = g_eamean[1];
    float t, m;
    t = zd.x + zd.x + fmaf(eax, We0.x, eay * We1.x);
    t = (t > 0.f) ? t : 0.2f * t; m = t * at.x;
    t = zd.y + zd.y + fmaf(eax, We0.y, eay * We1.y);
    t = (t > 0.f) ? t : 0.2f * t; m = fmaf(t, at.y, m);
    t = zd.z + zd.z + fmaf(eax, We0.z, eay * We1.z);
    t = (t > 0.f) ? t : 0.2f * t; m = fmaf(t, at.z, m);
    t = zd.w + zd.w + fmaf(eax, We0.w, eay * We1.w);
    t = (t > 0.f) ? t : 0.2f * t; m = fmaf(t, at.w, m);
#pragma unroll
    for (int o = 4; o >= 1; o >>= 1) m += __shfl_xor_sync(0xffffffffu, m, o);

    float denom = (half == 0) ? 1.f : 0.f;
    float4 acc;
    acc.x = (half == 0) ? zd.x : 0.f;
    acc.y = (half == 0) ? zd.y : 0.f;
    acc.z = (half == 0) ? zd.z : 0.f;
    acc.w = (half == 0) ? zd.w : 0.f;

    int idx = g_rowptr[dst], end = g_rowptr[dst + 1];

    // prologue: prefetch first epack quad
    int4 pA, pB;
    if (idx + 4 <= end) {
        pA = g_epack[idx + half];
        pB = g_epack[idx + 2 + half];
    }
    while (idx + 4 <= end) {
        // issue z gathers for the current quad
        float4 zA = __ldg((const float4*)&g_z[pA.x * 64 + ch]);
        float4 zB = __ldg((const float4*)&g_z[pB.x * 64 + ch]);
        float eAx = __int_as_float(pA.z), eAy = __int_as_float(pA.w);
        float eBx = __int_as_float(pB.z), eBy = __int_as_float(pB.w);
        idx += 4;
        // prefetch next quad's epack while z gathers are in flight
        int4 nA, nB;
        if (idx + 4 <= end) {
            nA = g_epack[idx + half];
            nB = g_epack[idx + 2 + half];
        }

        float pa, pb;
        t = zd.x + zA.x + fmaf(eAx, We0.x, eAy * We1.x);
        t = (t > 0.f) ? t : 0.2f * t; pa = t * at.x;
        t = zd.y + zA.y + fmaf(eAx, We0.y, eAy * We1.y);
        t = (t > 0.f) ? t : 0.2f * t; pa = fmaf(t, at.y, pa);
        t = zd.z + zA.z + fmaf(eAx, We0.z, eAy * We1.z);
        t = (t > 0.f) ? t : 0.2f * t; pa = fmaf(t, at.z, pa);
        t = zd.w + zA.w + fmaf(eAx, We0.w, eAy * We1.w);
        t = (t > 0.f) ? t : 0.2f * t; pa = fmaf(t, at.w, pa);

        t = zd.x + zB.x + fmaf(eBx, We0.x, eBy * We1.x);
        t = (t > 0.f) ? t : 0.2f * t; pb = t * at.x;
        t = zd.y + zB.y + fmaf(eBx, We0.y, eBy * We1.y);
        t = (t > 0.f) ? t : 0.2f * t; pb = fmaf(t, at.y, pb);
        t = zd.z + zB.z + fmaf(eBx, We0.z, eBy * We1.z);
        t = (t > 0.f) ? t : 0.2f * t; pb = fmaf(t, at.z, pb);
        t = zd.w + zB.w + fmaf(eBx, We0.w, eBy * We1.w);
        t = (t > 0.f) ? t : 0.2f * t; pb = fmaf(t, at.w, pb);

#pragma unroll
        for (int o = 4; o >= 1; o >>= 1) {
            pa += __shfl_xor_sync(0xffffffffu, pa, o);
            pb += __shfl_xor_sync(0xffffffffu, pb, o);
        }
        float wa = __expf(pa - m);
        float wb = __expf(pb - m);
        denom += wa + wb;
        acc.x = fmaf(wa, zA.x, acc.x); acc.x = fmaf(wb, zB.x, acc.x);
        acc.y = fmaf(wa, zA.y, acc.y); acc.y = fmaf(wb, zB.y, acc.y);
        acc.z = fmaf(wa, zA.z, acc.z); acc.z = fmaf(wb, zB.z, acc.z);
        acc.w = fmaf(wa, zA.w, acc.w); acc.w = fmaf(wb, zB.w, acc.w);
        pA = nA; pB = nB;
    }
    // remainder: up to 3 edges, 2 at a time with validity guard
    for (; idx < end; idx += 2) {
        int e = idx + half;
        bool valid = e < end;
        int4 pR = g_epack[valid ? e : (end - 1)];
        float4 zA = __ldg((const float4*)&g_z[pR.x * 64 + ch]);
        float eAx = __int_as_float(pR.z), eAy = __int_as_float(pR.w);
        float pa;
        t = zd.x + zA.x + fmaf(eAx, We0.x, eAy * We1.x);
        t = (t > 0.f) ? t : 0.2f * t; pa = t * at.x;
        t = zd.y + zA.y + fmaf(eAx, We0.y, eAy * We1.y);
        t = (t > 0.f) ? t : 0.2f * t; pa = fmaf(t, at.y, pa);
        t = zd.z + zA.z + fmaf(eAx, We0.z, eAy * We1.z);
        t = (t > 0.f) ? t : 0.2f * t; pa = fmaf(t, at.z, pa);
        t = zd.w + zA.w + fmaf(eAx, We0.w, eAy * We1.w);
        t = (t > 0.f) ? t : 0.2f * t; pa = fmaf(t, at.w, pa);
#pragma unroll
        for (int o = 4; o >= 1; o >>= 1) pa += __shfl_xor_sync(0xffffffffu, pa, o);
        float wa = valid ? __expf(pa - m) : 0.f;
        denom += wa;
        acc.x = fmaf(wa, zA.x, acc.x);
        acc.y = fmaf(wa, zA.y, acc.y);
        acc.z = fmaf(wa, zA.z, acc.z);
        acc.w = fmaf(wa, zA.w, acc.w);
    }
    // merge half-warps (shared m -> plain addition)
    denom += __shfl_xor_sync(0xffffffffu, denom, 16);
    acc.x += __shfl_xor_sync(0xffffffffu, acc.x, 16);
    acc.y += __shfl_xor_sync(0xffffffffu, acc.y, 16);
    acc.z += __shfl_xor_sync(0xffffffffu, acc.z, 16);
    acc.w += __shfl_xor_sync(0xffffffffu, acc.w, 16);

    if (half == 0) {
        float inv = __fdividef(1.f, denom + 1e-16f);
        float4 b4 = *(const float4*)&bias[ch];
        float o; float4 h;
        o = fmaf(acc.x, inv, b4.x); h.x = (o > 0.f) ? o : expm1f(o);
        o = fmaf(acc.y, inv, b4.y); h.y = (o > 0.f) ? o : expm1f(o);
        o = fmaf(acc.z, inv, b4.z); h.z = (o > 0.f) ? o : expm1f(o);
        o = fmaf(acc.w, inv, b4.w); h.w = (o > 0.f) ? o : expm1f(o);
        *(float4*)&g_h[dst * 64 + ch] = h;
        if (destp && dst == destp[0]) *(float4*)&g_hdest[ch] = h;
    }
}

// ============================================================
// 4/6) register-tiled GEMM on device globals:
// mode 0: g_z[N,64]  = g_h[N,64] @ W (64x64 row-major) + bias
// mode 1: g_uv[N,64] = g_h[N,64] @ W' where
//         W'[k][j] = j<32 ? W[k*32+j] : W[(64+k)*32+j-32]   (no bias)
// ============================================================
__global__ void __launch_bounds__(128)
k_gemv(const float* __restrict__ W, const float* __restrict__ bias,
       int N, int mode) {
    __shared__ __align__(16) float sW[64 * 64];
    __shared__ __align__(16) float sA[64 * 68];

    for (int idx = threadIdx.x; idx < 4096; idx += 128) {
        int k = idx >> 6, j = idx & 63;
        sW[idx] = (mode == 0) ? W[idx]
                : ((j < 32) ? W[k * 32 + j] : W[(64 + k) * 32 + (j - 32)]);
    }
    int nbase = blockIdx.x * 64;
    for (int idx = threadIdx.x; idx < 64 * 16; idx += 128) {
        int n = idx >> 4, k4 = idx & 15;
        float4 av = (nbase + n < N)
            ? *(const float4*)&g_h[(nbase + n) * 64 + k4 * 4]
            : make_float4(0.f, 0.f, 0.f, 0.f);
        *(float4*)&sA[n * 68 + k4 * 4] = av;
    }
    __syncthreads();

    int cg = threadIdx.x & 7;        // channels cg*8 .. cg*8+7
    int ng = threadIdx.x >> 3;       // nodes ng*4 .. ng*4+3
    __align__(16) unsigned long long acc[4][4];
#pragma unroll
    for (int i = 0; i < 4; i++)
#pragma unroll
        for (int j = 0; j < 4; j++) acc[i][j] = 0ull;

    for (int k4 = 0; k4 < 16; k4++) {
        float4 a4[4];
#pragma unroll
        for (int i = 0; i < 4; i++)
            a4[i] = *(const float4*)&sA[(ng * 4 + i) * 68 + k4 * 4];
#pragma unroll
        for (int kk = 0; kk < 4; kk++) {
            int k = k4 * 4 + kk;
            ulonglong2 wl = *(const ulonglong2*)&sW[k * 64 + cg * 8];
            ulonglong2 wh = *(const ulonglong2*)&sW[k * 64 + cg * 8 + 4];
#pragma unroll
            for (int i = 0; i < 4; i++) {
                float a = (kk == 0) ? a4[i].x : (kk == 1) ? a4[i].y
                        : (kk == 2) ? a4[i].z : a4[i].w;
                unsigned long long aa = pack2(a, a);
                acc[i][0] = fma2(aa, wl.x, acc[i][0]);
                acc[i][1] = fma2(aa, wl.y, acc[i][1]);
                acc[i][2] = fma2(aa, wh.x, acc[i][2]);
                acc[i][3] = fma2(aa, wh.y, acc[i][3]);
            }
        }
    }
    if (mode == 0) {
        ulonglong2 b0 = *(const ulonglong2*)&bias[cg * 8];
        ulonglong2 b1v = *(const ulonglong2*)&bias[cg * 8 + 4];
#pragma unroll
        for (int i = 0; i < 4; i++) {
            acc[i][0] = add2(acc[i][0], b0.x);
            acc[i][1] = add2(acc[i][1], b0.y);
            acc[i][2] = add2(acc[i][2], b1v.x);
            acc[i][3] = add2(acc[i][3], b1v.y);
        }
    }
    float* C = (mode == 0) ? g_z : g_uv;
#pragma unroll
    for (int i = 0; i < 4; i++) {
        int n = nbase + ng * 4 + i;
        if (n < N) {
            *(float4*)&C[n * 64 + cg * 8]     = *(float4*)&acc[i][0];
            *(float4*)&C[n * 64 + cg * 8 + 4] = *(float4*)&acc[i][2];
        }
    }
}

// ============================================================
// 7) edge MLP, warp per dst node, 4 edges x 8 lanes per iteration,
// with epack prefetch pipelining (breaks epack->u chain).
// ============================================================
__global__ void __launch_bounds__(256)
k_edge(const float* __restrict__ Wm1, const float* __restrict__ bm1,
       const float* __restrict__ Wm2, const float* __restrict__ bm2,
       float* __restrict__ out, int N) {
    __shared__ float sg[32];
    if (threadIdx.x < 32) {
        int j = threadIdx.x;
        float acc = bm1[j];
#pragma unroll
        for (int k = 0; k < 64; k++)
            acc = fmaf(g_hdest[k], Wm1[(128 + k) * 32 + j], acc);
        sg[j] = acc;
    }
    __syncthreads();

    int warp = (blockIdx.x * blockDim.x + threadIdx.x) >> 5;
    int lane = threadIdx.x & 31;
    if (warp >= N) return;
    int dst = warp;
    int g = lane >> 3;          // edge slot 0..3
    int l = lane & 7;           // channel block: channels [4l, 4l+4)

    float4 v4 = __ldg((const float4*)&g_uv[dst * 64 + 32 + l * 4]);
    float4 gv = *(const float4*)&sg[l * 4];
    float4 w0 = __ldg(&((const float4*)&Wm1[192 * 32])[l]);
    float4 w1 = __ldg(&((const float4*)&Wm1[193 * 32])[l]);
    float4 w2 = __ldg(&((const float4*)Wm2)[l]);
    float bm2v = bm2[0];
    float bx = v4.x + gv.x, by = v4.y + gv.y;
    float bz = v4.z + gv.z, bw = v4.w + gv.w;

    int start = g_rowptr[dst], end = g_rowptr[dst + 1];
    if (start >= end) return;
    int e0 = start + g;
    int4 pk = g_epack[(e0 < end) ? e0 : (end - 1)];
    for (int idx = start; idx < end; idx += 4) {
        int e = idx + g;
        bool valid = e < end;
        float4 u4 = __ldg((const float4*)&g_uv[pk.x * 64 + l * 4]);
        float ax = __int_as_float(pk.z), ay = __int_as_float(pk.w);
        int perm = pk.y;
        // prefetch next quad's epack
        int en = idx + 4 + g;
        if (idx + 4 < end) pk = g_epack[(en < end) ? en : (end - 1)];

        float m0 = u4.x + bx + fmaf(ax, w0.x, ay * w1.x);
        float m1 = u4.y + by + fmaf(ax, w0.y, ay * w1.y);
        float m2 = u4.z + bz + fmaf(ax, w0.z, ay * w1.z);
        float m3 = u4.w + bw + fmaf(ax, w0.w, ay * w1.w);
        m0 = fmaxf(m0, 0.f); m1 = fmaxf(m1, 0.f);
        m2 = fmaxf(m2, 0.f); m3 = fmaxf(m3, 0.f);
        float s = fmaf(m0, w2.x, fmaf(m1, w2.y, fmaf(m2, w2.z, m3 * w2.w)));
        s += __shfl_xor_sync(0xffffffffu, s, 4);
        s += __shfl_xor_sync(0xffffffffu, s, 2);
        s += __shfl_xor_sync(0xffffffffu, s, 1);
        if (valid && l == 0) out[perm] = s + bm2v;
    }
}

// ============================================================
extern "C" void kernel_launch(void* const* d_in, const int* in_sizes, int n_in,
                              void* d_out, int out_size) {
    const float* x     = (const float*)d_in[0];
    const int*   ei    = (const int*)d_in[1];
    const float* ea    = (const float*)d_in[2];
    const int*   dest  = (const int*)d_in[3];
    const float* W0    = (const float*)d_in[4];
    const float* b0    = (const float*)d_in[5];
    const float* We0   = (const float*)d_in[6];
    const float* att0  = (const float*)d_in[7];
    const float* bias0 = (const float*)d_in[8];
    const float* W1    = (const float*)d_in[9];
    const float* b1    = (const float*)d_in[10];
    const float* We1   = (const float*)d_in[11];
    const float* att1  = (const float*)d_in[12];
    const float* bias1 = (const float*)d_in[13];
    const float* Wm1   = (const float*)d_in[14];
    const float* bm1   = (const float*)d_in[15];
    const float* Wm2   = (const float*)d_in[16];
    const float* bm2   = (const float*)d_in[17];

    int N = in_sizes[0] / 2;
    int E = in_sizes[1] / 2;

    const int TB = 256;
    int gE    = (E + TB - 1) / TB;
    int gN8   = (N * 8 + TB - 1) / TB;
    int gAgg  = (N * 32 + TB - 1) / TB;
    int gGemv = (N + 63) / 64;
    int nSB   = (N + 255) / 256;

    k_easum_hist<<<512, TB>>>(ei, (const float2*)ea, E);                // 0
    k_scan<<<nSB, 256>>>(N, E);                                         // 1
    k_scatter_z0<<<gE + gN8, TB>>>(ei, (const float2*)ea,
                                   (const float2*)x, W0, b0, N, E, gE); // 2
    // layer 0
    k_agg<<<gAgg, TB>>>(We0, att0, bias0, (const int*)0, N);            // 3 (profiled)
    k_gemv<<<gGemv, 128>>>(W1, b1, N, 0);                               // 4
    // layer 1
    k_agg<<<gAgg, TB>>>(We1, att1, bias1, dest, N);                     // 5
    k_gemv<<<gGemv, 128>>>(Wm1, (const float*)0, N, 1);                 // 6
    // edge scoring head
    k_edge<<<gAgg, TB>>>(Wm1, bm1, Wm2, bm2, (float*)d_out, N);         // 7
}

// round 11
// speedup vs baseline: 1.3872x; 1.0002x over previous
#include <cuda_runtime.h>
#include <math.h>

// Problem max sizes (N=50000, E=800000)
#define NMAX 50000
#define EMAX 800000

// ---- static device scratch (zero-initialized at module load; the
// pipeline re-zeroes cnt/tile/tilectr/easum each run in k_scatter_z0) ----
__device__ float  g_z[NMAX * 64];      // z of current layer (z0, then z1)
__device__ float  g_h[NMAX * 64];      // h of current layer
__device__ float  g_uv[NMAX * 64];     // [u | v] per node
__device__ __align__(16) float g_hdest[64];
__device__ double g_easum[2];
__device__ float  g_eamean[2];
// CSR by dst: packed edge payload {src, perm, ea.x(bits), ea.y(bits)}
__device__ int    g_cnt[NMAX];
__device__ int    g_rowptr[NMAX + 1];
__device__ int    g_rowcur[NMAX];
__device__ int4   g_epack[EMAX];
// decoupled-lookback scan state
__device__ unsigned long long g_tile[256];
__device__ int    g_tilectr;

// ---- packed fp32x2 helpers (Blackwell FFMA2) ----
__device__ __forceinline__ unsigned long long pack2(float a, float b) {
    unsigned long long r;
    asm("mov.b64 %0, {%1, %2};" : "=l"(r) : "f"(a), "f"(b));
    return r;
}
__device__ __forceinline__ void unpack2(float& lo, float& hi,
                                        unsigned long long v) {
    asm("mov.b64 {%0, %1}, %2;" : "=f"(lo), "=f"(hi) : "l"(v));
}
__device__ __forceinline__ unsigned long long fma2(unsigned long long a,
                                                   unsigned long long b,
                                                   unsigned long long c) {
    unsigned long long d;
    asm("fma.rn.f32x2 %0, %1, %2, %3;" : "=l"(d) : "l"(a), "l"(b), "l"(c));
    return d;
}
__device__ __forceinline__ unsigned long long mul2(unsigned long long a,
                                                   unsigned long long b) {
    unsigned long long d;
    asm("mul.rn.f32x2 %0, %1, %2;" : "=l"(d) : "l"(a), "l"(b));
    return d;
}
__device__ __forceinline__ unsigned long long add2(unsigned long long a,
                                                   unsigned long long b) {
    unsigned long long d;
    asm("add.rn.f32x2 %0, %1, %2;" : "=l"(d) : "l"(a), "l"(b));
    return d;
}

// ============================================================
// 0) fused: edge_attr column sums (double) + dst histogram
// ============================================================
__global__ void k_easum_hist(const int* __restrict__ ei,
                             const float2* __restrict__ ea, int E) {
    double d0 = 0.0, d1 = 0.0;
    for (int i = blockIdx.x * blockDim.x + threadIdx.x; i < E;
         i += gridDim.x * blockDim.x) {
        float2 v = ea[i];
        d0 += (double)v.x; d1 += (double)v.y;
        atomicAdd(&g_cnt[ei[E + i]], 1);
    }
    __shared__ double sh0[256], sh1[256];
    int t = threadIdx.x;
    sh0[t] = d0; sh1[t] = d1;
    __syncthreads();
    for (int ofs = 128; ofs > 0; ofs >>= 1) {
        if (t < ofs) { sh0[t] += sh0[t + ofs]; sh1[t] += sh1[t + ofs]; }
        __syncthreads();
    }
    if (t == 0) { atomicAdd(&g_easum[0], sh0[0]); atomicAdd(&g_easum[1], sh1[0]); }
}

// ============================================================
// 1) exclusive scan of g_cnt (decoupled lookback) + eamean
// ============================================================
__global__ void __launch_bounds__(256) k_scan(int N, int E) {
    __shared__ int sbid;
    __shared__ int swsum[8];
    __shared__ int sexcl;
    if (threadIdx.x == 0) sbid = atomicAdd(&g_tilectr, 1);
    __syncthreads();
    int bid = sbid;
    if (bid == 0 && threadIdx.x < 2)
        g_eamean[threadIdx.x] = (float)(g_easum[threadIdx.x] / (double)E);

    int i = bid * 256 + threadIdx.x;
    int v = (i < N) ? g_cnt[i] : 0;
    int lane = threadIdx.x & 31, w = threadIdx.x >> 5;
    int s = v;
#pragma unroll
    for (int o = 1; o < 32; o <<= 1) {
        int t = __shfl_up_sync(0xffffffffu, s, o);
        if (lane >= o) s += t;
    }
    if (lane == 31) swsum[w] = s;
    __syncthreads();
    if (w == 0) {
        int ws = (lane < 8) ? swsum[lane] : 0;
#pragma unroll
        for (int o = 1; o < 8; o <<= 1) {
            int t = __shfl_up_sync(0xffffffffu, ws, o);
            if (lane >= o) ws += t;
        }
        if (lane < 8) swsum[lane] = ws;
    }
    __syncthreads();
    int incl = s + (w > 0 ? swsum[w - 1] : 0);
    int btotal = swsum[7];

    if (threadIdx.x == 0) {
        unsigned long long word = (bid == 0)
            ? ((2ull << 32) | (unsigned)btotal)
            : ((1ull << 32) | (unsigned)btotal);
        atomicExch(&g_tile[bid], word);
    }

    if (bid > 0 && w == 0) {
        int excl = 0;
        int look = bid - 1 - lane;
        for (;;) {
            unsigned long long word = (look >= 0)
                ? atomicAdd(&g_tile[look], 0ull) : (2ull << 32);
            unsigned st = (unsigned)(word >> 32);
            unsigned pend = __ballot_sync(0xffffffffu, st == 0u);
            if (pend) continue;
            unsigned pre = __ballot_sync(0xffffffffu, st == 2u);
            int fp = __ffs(pre) - 1;
            int val = (int)(word & 0xffffffffu);
            if (fp >= 0) {
                int contrib = (lane <= fp && look >= 0) ? val : 0;
#pragma unroll
                for (int o = 16; o > 0; o >>= 1)
                    contrib += __shfl_xor_sync(0xffffffffu, contrib, o);
                excl += contrib;
                break;
            } else {
                int contrib = (look >= 0) ? val : 0;
#pragma unroll
                for (int o = 16; o > 0; o >>= 1)
                    contrib += __shfl_xor_sync(0xffffffffu, contrib, o);
                excl += contrib;
                look -= 32;
            }
        }
        if (lane == 0) {
            atomicExch(&g_tile[bid], (2ull << 32) | (unsigned)(excl + btotal));
            sexcl = excl;
        }
    } else if (threadIdx.x == 0) {
        sexcl = 0;
    }
    __syncthreads();
    int excl = sexcl;
    if (i < N) {
        int ip = excl + incl;
        g_rowptr[i + 1] = ip;
        g_rowcur[i] = ip - v;
    }
    if (i == 0) g_rowptr[0] = 0;
}

// ============================================================
// 2) fused: packed CSR scatter + vectorized z0 = x@W0+b0
//    + re-zero cnt/tile/tilectr/easum for the next run
// ============================================================
__global__ void k_scatter_z0(const int* __restrict__ ei,
                             const float2* __restrict__ ea,
                             const float2* __restrict__ x,
                             const float* __restrict__ W0,
                             const float* __restrict__ b0,
                             int N, int E, int gE) {
    if ((int)blockIdx.x < gE) {
        int e = blockIdx.x * 256 + threadIdx.x;
        if (e < E) {
            int dst = ei[E + e];
            int pos = atomicAdd(&g_rowcur[dst], 1);
            float2 a = ea[e];
            g_epack[pos] = make_int4(ei[e], e, __float_as_int(a.x),
                                     __float_as_int(a.y));
        }
    } else {
        int i = (blockIdx.x - gE) * 256 + threadIdx.x;   // [0, N*8)
        // re-zero scan/hist state (last readers already ran)
        if (i < N) g_cnt[i] = 0;
        if (i < 256) g_tile[i] = 0ull;
        if (i == 0) { g_tilectr = 0; g_easum[0] = 0.0; g_easum[1] = 0.0; }
        if (i < N * 8) {
            int n = i >> 3, j = (i & 7) * 8;
            float2 xv = x[n];
            float4 w0a = *(const float4*)&W0[j];
            float4 w0b = *(const float4*)&W0[j + 4];
            float4 w1a = *(const float4*)&W0[64 + j];
            float4 w1b = *(const float4*)&W0[64 + j + 4];
            float4 ba  = *(const float4*)&b0[j];
            float4 bb  = *(const float4*)&b0[j + 4];
            float4 r0, r1;
            r0.x = fmaf(xv.x, w0a.x, fmaf(xv.y, w1a.x, ba.x));
            r0.y = fmaf(xv.x, w0a.y, fmaf(xv.y, w1a.y, ba.y));
            r0.z = fmaf(xv.x, w0a.z, fmaf(xv.y, w1a.z, ba.z));
            r0.w = fmaf(xv.x, w0a.w, fmaf(xv.y, w1a.w, ba.w));
            r1.x = fmaf(xv.x, w0b.x, fmaf(xv.y, w1b.x, bb.x));
            r1.y = fmaf(xv.x, w0b.y, fmaf(xv.y, w1b.y, bb.y));
            r1.z = fmaf(xv.x, w0b.z, fmaf(xv.y, w1b.z, bb.z));
            r1.w = fmaf(xv.x, w0b.w, fmaf(xv.y, w1b.w, bb.w));
            *(float4*)&g_z[n * 64 + j]     = r0;
            *(float4*)&g_z[n * 64 + j + 4] = r1;
        }
    }
}

// ============================================================
// 3/5) GATv2 aggregation: fixed softmax reference + half-warp edge
// parallelism + epack prefetch + PACKED f32x2 logit/accum math.
// Warp = dst node; lane = half*16+q; q owns channels 4q..4q+3
// (two f32x2 pairs). Leaky+dot scalar after one unpack.
// ============================================================
__global__ void __launch_bounds__(256)
k_agg(const float* __restrict__ We, const float* __restrict__ att,
      const float* __restrict__ bias, const int* __restrict__ destp, int N) {
    int dst = (blockIdx.x * blockDim.x + threadIdx.x) >> 5;
    int lane = threadIdx.x & 31;
    if (dst >= N) return;
    int half = lane >> 4;
    int q = lane & 15;
    int ch = q * 4;

    // packed weight pairs
    ulonglong2 We0p = __ldg((const ulonglong2*)&We[ch]);
    ulonglong2 We1p = __ldg((const ulonglong2*)&We[64 + ch]);
    float4 at = *(const float4*)&att[ch];
    ulonglong2 zdp = __ldg((const ulonglong2*)&g_z[dst * 64 + ch]);
    float zd0, zd1, zd2, zd3;
    unpack2(zd0, zd1, zdp.x);
    unpack2(zd2, zd3, zdp.y);

    // self-loop logit = fixed softmax reference m (scalar, once)
    float eax = g_eamean[0], eay = g_eamean[1];
    {
        unsigned long long ex2 = pack2(eax, eax), ey2 = pack2(eay, eay);
        unsigned long long e01 = fma2(ex2, We0p.x, mul2(ey2, We1p.x));
        unsigned long long e23 = fma2(ex2, We0p.y, mul2(ey2, We1p.y));
        unsigned long long t01 = add2(add2(zdp.x, zdp.x), e01);
        unsigned long long t23 = add2(add2(zdp.y, zdp.y), e23);
        float t0, t1, t2, t3;
        unpack2(t0, t1, t01); unpack2(t2, t3, t23);
        t0 = (t0 > 0.f) ? t0 : 0.2f * t0;
        t1 = (t1 > 0.f) ? t1 : 0.2f * t1;
        t2 = (t2 > 0.f) ? t2 : 0.2f * t2;
        t3 = (t3 > 0.f) ? t3 : 0.2f * t3;
        float mm = fmaf(t0, at.x, fmaf(t1, at.y, fmaf(t2, at.z, t3 * at.w)));
#pragma unroll
        for (int o = 4; o >= 1; o >>= 1)
            mm += __shfl_xor_sync(0xffffffffu, mm, o);
        eax = mm;   // reuse reg: eax now holds m
    }
    float m = eax;

    float denom = (half == 0) ? 1.f : 0.f;
    unsigned long long acc01, acc23;
    if (half == 0) { acc01 = zdp.x; acc23 = zdp.y; }
    else           { acc01 = pack2(0.f, 0.f); acc23 = acc01; }

    int idx = g_rowptr[dst], end = g_rowptr[dst + 1];

    int4 pA, pB;
    if (idx + 4 <= end) {
        pA = g_epack[idx + half];
        pB = g_epack[idx + 2 + half];
    }
    while (idx + 4 <= end) {
        ulonglong2 zA = __ldg((const ulonglong2*)&g_z[pA.x * 64 + ch]);
        ulonglong2 zB = __ldg((const ulonglong2*)&g_z[pB.x * 64 + ch]);
        float eAx = __int_as_float(pA.z), eAy = __int_as_float(pA.w);
        float eBx = __int_as_float(pB.z), eBy = __int_as_float(pB.w);
        idx += 4;
        int4 nA, nB;
        if (idx + 4 <= end) {
            nA = g_epack[idx + half];
            nB = g_epack[idx + 2 + half];
        }

        // edge A logit (packed)
        unsigned long long exA = pack2(eAx, eAx), eyA = pack2(eAy, eAy);
        unsigned long long a01 = add2(add2(zdp.x, zA.x),
                                      fma2(exA, We0p.x, mul2(eyA, We1p.x)));
        unsigned long long a23 = add2(add2(zdp.y, zA.y),
                                      fma2(exA, We0p.y, mul2(eyA, We1p.y)));
        // edge B logit (packed)
        unsigned long long exB = pack2(eBx, eBx), eyB = pack2(eBy, eBy);
        unsigned long long b01 = add2(add2(zdp.x, zB.x),
                                      fma2(exB, We0p.x, mul2(eyB, We1p.x)));
        unsigned long long b23 = add2(add2(zdp.y, zB.y),
                                      fma2(exB, We0p.y, mul2(eyB, We1p.y)));

        float a0, a1, a2, a3, b0_, b1_, b2_, b3_;
        unpack2(a0, a1, a01); unpack2(a2, a3, a23);
        unpack2(b0_, b1_, b01); unpack2(b2_, b3_, b23);
        a0 = (a0 > 0.f) ? a0 : 0.2f * a0;
        a1 = (a1 > 0.f) ? a1 : 0.2f * a1;
        a2 = (a2 > 0.f) ? a2 : 0.2f * a2;
        a3 = (a3 > 0.f) ? a3 : 0.2f * a3;
        b0_ = (b0_ > 0.f) ? b0_ : 0.2f * b0_;
        b1_ = (b1_ > 0.f) ? b1_ : 0.2f * b1_;
        b2_ = (b2_ > 0.f) ? b2_ : 0.2f * b2_;
        b3_ = (b3_ > 0.f) ? b3_ : 0.2f * b3_;
        float pa = fmaf(a0, at.x, fmaf(a1, at.y, fmaf(a2, at.z, a3 * at.w)));
        float pb = fmaf(b0_, at.x, fmaf(b1_, at.y, fmaf(b2_, at.z, b3_ * at.w)));

#pragma unroll
        for (int o = 4; o >= 1; o >>= 1) {
            pa += __shfl_xor_sync(0xffffffffu, pa, o);
            pb += __shfl_xor_sync(0xffffffffu, pb, o);
        }
        float wa = __expf(pa - m);
        float wb = __expf(pb - m);
        denom += wa + wb;
        unsigned long long wa2 = pack2(wa, wa);
        unsigned long long wb2 = pack2(wb, wb);
        acc01 = fma2(wa2, zA.x, acc01);
        acc23 = fma2(wa2, zA.y, acc23);
        acc01 = fma2(wb2, zB.x, acc01);
        acc23 = fma2(wb2, zB.y, acc23);
        pA = nA; pB = nB;
    }
    // remainder: up to 3 edges, 2 at a time with validity guard
    for (; idx < end; idx += 2) {
        int e = idx + half;
        bool valid = e < end;
        int4 pR = g_epack[valid ? e : (end - 1)];
        ulonglong2 zA = __ldg((const ulonglong2*)&g_z[pR.x * 64 + ch]);
        float eAx = __int_as_float(pR.z), eAy = __int_as_float(pR.w);
        unsigned long long exA = pack2(eAx, eAx), eyA = pack2(eAy, eAy);
        unsigned long long a01 = add2(add2(zdp.x, zA.x),
                                      fma2(exA, We0p.x, mul2(eyA, We1p.x)));
        unsigned long long a23 = add2(add2(zdp.y, zA.y),
                                      fma2(exA, We0p.y, mul2(eyA, We1p.y)));
        float a0, a1, a2, a3;
        unpack2(a0, a1, a01); unpack2(a2, a3, a23);
        a0 = (a0 > 0.f) ? a0 : 0.2f * a0;
        a1 = (a1 > 0.f) ? a1 : 0.2f * a1;
        a2 = (a2 > 0.f) ? a2 : 0.2f * a2;
        a3 = (a3 > 0.f) ? a3 : 0.2f * a3;
        float pa = fmaf(a0, at.x, fmaf(a1, at.y, fmaf(a2, at.z, a3 * at.w)));
#pragma unroll
        for (int o = 4; o >= 1; o >>= 1) pa += __shfl_xor_sync(0xffffffffu, pa, o);
        float wa = valid ? __expf(pa - m) : 0.f;
        denom += wa;
        unsigned long long wa2 = pack2(wa, wa);
        acc01 = fma2(wa2, zA.x, acc01);
        acc23 = fma2(wa2, zA.y, acc23);
    }
    // merge half-warps (shared m -> plain addition)
    float ax0, ax1, ax2, ax3;
    unpack2(ax0, ax1, acc01);
    unpack2(ax2, ax3, acc23);
    denom += __shfl_xor_sync(0xffffffffu, denom, 16);
    ax0 += __shfl_xor_sync(0xffffffffu, ax0, 16);
    ax1 += __shfl_xor_sync(0xffffffffu, ax1, 16);
    ax2 += __shfl_xor_sync(0xffffffffu, ax2, 16);
    ax3 += __shfl_xor_sync(0xffffffffu, ax3, 16);

    if (half == 0) {
        float inv = __fdividef(1.f, denom + 1e-16f);
        float4 b4 = *(const float4*)&bias[ch];
        float o; float4 h;
        o = fmaf(ax0, inv, b4.x); h.x = (o > 0.f) ? o : expm1f(o);
        o = fmaf(ax1, inv, b4.y); h.y = (o > 0.f) ? o : expm1f(o);
        o = fmaf(ax2, inv, b4.z); h.z = (o > 0.f) ? o : expm1f(o);
        o = fmaf(ax3, inv, b4.w); h.w = (o > 0.f) ? o : expm1f(o);
        *(float4*)&g_h[dst * 64 + ch] = h;
        if (destp && dst == destp[0]) *(float4*)&g_hdest[ch] = h;
    }
}

// ============================================================
// 4/6) register-tiled GEMM on device globals:
// mode 0: g_z[N,64]  = g_h[N,64] @ W (64x64 row-major) + bias
// mode 1: g_uv[N,64] = g_h[N,64] @ W' where
//         W'[k][j] = j<32 ? W[k*32+j] : W[(64+k)*32+j-32]   (no bias)
// ============================================================
__global__ void __launch_bounds__(128)
k_gemv(const float* __restrict__ W, const float* __restrict__ bias,
       int N, int mode) {
    __shared__ __align__(16) float sW[64 * 64];
    __shared__ __align__(16) float sA[64 * 68];

    for (int idx = threadIdx.x; idx < 4096; idx += 128) {
        int k = idx >> 6, j = idx & 63;
        sW[idx] = (mode == 0) ? W[idx]
                : ((j < 32) ? W[k * 32 + j] : W[(64 + k) * 32 + (j - 32)]);
    }
    int nbase = blockIdx.x * 64;
    for (int idx = threadIdx.x; idx < 64 * 16; idx += 128) {
        int n = idx >> 4, k4 = idx & 15;
        float4 av = (nbase + n < N)
            ? *(const float4*)&g_h[(nbase + n) * 64 + k4 * 4]
            : make_float4(0.f, 0.f, 0.f, 0.f);
        *(float4*)&sA[n * 68 + k4 * 4] = av;
    }
    __syncthreads();

    int cg = threadIdx.x & 7;        // channels cg*8 .. cg*8+7
    int ng = threadIdx.x >> 3;       // nodes ng*4 .. ng*4+3
    __align__(16) unsigned long long acc[4][4];
#pragma unroll
    for (int i = 0; i < 4; i++)
#pragma unroll
        for (int j = 0; j < 4; j++) acc[i][j] = 0ull;

    for (int k4 = 0; k4 < 16; k4++) {
        float4 a4[4];
#pragma unroll
        for (int i = 0; i < 4; i++)
            a4[i] = *(const float4*)&sA[(ng * 4 + i) * 68 + k4 * 4];
#pragma unroll
        for (int kk = 0; kk < 4; kk++) {
            int k = k4 * 4 + kk;
            ulonglong2 wl = *(const ulonglong2*)&sW[k * 64 + cg * 8];
            ulonglong2 wh = *(const ulonglong2*)&sW[k * 64 + cg * 8 + 4];
#pragma unroll
            for (int i = 0; i < 4; i++) {
                float a = (kk == 0) ? a4[i].x : (kk == 1) ? a4[i].y
                        : (kk == 2) ? a4[i].z : a4[i].w;
                unsigned long long aa = pack2(a, a);
                acc[i][0] = fma2(aa, wl.x, acc[i][0]);
                acc[i][1] = fma2(aa, wl.y, acc[i][1]);
                acc[i][2] = fma2(aa, wh.x, acc[i][2]);
                acc[i][3] = fma2(aa, wh.y, acc[i][3]);
            }
        }
    }
    if (mode == 0) {
        ulonglong2 b0 = *(const ulonglong2*)&bias[cg * 8];
        ulonglong2 b1v = *(const ulonglong2*)&bias[cg * 8 + 4];
#pragma unroll
        for (int i = 0; i < 4; i++) {
            acc[i][0] = add2(acc[i][0], b0.x);
            acc[i][1] = add2(acc[i][1], b0.y);
            acc[i][2] = add2(acc[i][2], b1v.x);
            acc[i][3] = add2(acc[i][3], b1v.y);
        }
    }
    float* C = (mode == 0) ? g_z : g_uv;
#pragma unroll
    for (int i = 0; i < 4; i++) {
        int n = nbase + ng * 4 + i;
        if (n < N) {
            *(float4*)&C[n * 64 + cg * 8]     = *(float4*)&acc[i][0];
            *(float4*)&C[n * 64 + cg * 8 + 4] = *(float4*)&acc[i][2];
        }
    }
}

// ============================================================
// 7) edge MLP, warp per dst node, 4 edges x 8 lanes per iteration,
// with epack prefetch pipelining (breaks epack->u chain).
// ============================================================
__global__ void __launch_bounds__(256)
k_edge(const float* __restrict__ Wm1, const float* __restrict__ bm1,
       const float* __restrict__ Wm2, const float* __restrict__ bm2,
       float* __restrict__ out, int N) {
    __shared__ float sg[32];
    if (threadIdx.x < 32) {
        int j = threadIdx.x;
        float acc = bm1[j];
#pragma unroll
        for (int k = 0; k < 64; k++)
            acc = fmaf(g_hdest[k], Wm1[(128 + k) * 32 + j], acc);
        sg[j] = acc;
    }
    __syncthreads();

    int warp = (blockIdx.x * blockDim.x + threadIdx.x) >> 5;
    int lane = threadIdx.x & 31;
    if (warp >= N) return;
    int dst = warp;
    int g = lane >> 3;          // edge slot 0..3
    int l = lane & 7;           // channel block: channels [4l, 4l+4)

    float4 v4 = __ldg((const float4*)&g_uv[dst * 64 + 32 + l * 4]);
    float4 gv = *(const float4*)&sg[l * 4];
    float4 w0 = __ldg(&((const float4*)&Wm1[192 * 32])[l]);
    float4 w1 = __ldg(&((const float4*)&Wm1[193 * 32])[l]);
    float4 w2 = __ldg(&((const float4*)Wm2)[l]);
    float bm2v = bm2[0];
    float bx = v4.x + gv.x, by = v4.y + gv.y;
    float bz = v4.z + gv.z, bw = v4.w + gv.w;

    int start = g_rowptr[dst], end = g_rowptr[dst + 1];
    if (start >= end) return;
    int e0 = start + g;
    int4 pk = g_epack[(e0 < end) ? e0 : (end - 1)];
    for (int idx = start; idx < end; idx += 4) {
        int e = idx + g;
        bool valid = e < end;
        float4 u4 = __ldg((const float4*)&g_uv[pk.x * 64 + l * 4]);
        float ax = __int_as_float(pk.z), ay = __int_as_float(pk.w);
        int perm = pk.y;
        // prefetch next quad's epack
        int en = idx + 4 + g;
        if (idx + 4 < end) pk = g_epack[(en < end) ? en : (end - 1)];

        float m0 = u4.x + bx + fmaf(ax, w0.x, ay * w1.x);
        float m1 = u4.y + by + fmaf(ax, w0.y, ay * w1.y);
        float m2 = u4.z + bz + fmaf(ax, w0.z, ay * w1.z);
        float m3 = u4.w + bw + fmaf(ax, w0.w, ay * w1.w);
        m0 = fmaxf(m0, 0.f); m1 = fmaxf(m1, 0.f);
        m2 = fmaxf(m2, 0.f); m3 = fmaxf(m3, 0.f);
        float s = fmaf(m0, w2.x, fmaf(m1, w2.y, fmaf(m2, w2.z, m3 * w2.w)));
        s += __shfl_xor_sync(0xffffffffu, s, 4);
        s += __shfl_xor_sync(0xffffffffu, s, 2);
        s += __shfl_xor_sync(0xffffffffu, s, 1);
        if (valid && l == 0) out[perm] = s + bm2v;
    }
}

// ============================================================
extern "C" void kernel_launch(void* const* d_in, const int* in_sizes, int n_in,
                              void* d_out, int out_size) {
    const float* x     = (const float*)d_in[0];
    const int*   ei    = (const int*)d_in[1];
    const float* ea    = (const float*)d_in[2];
    const int*   dest  = (const int*)d_in[3];
    const float* W0    = (const float*)d_in[4];
    const float* b0    = (const float*)d_in[5];
    const float* We0   = (const float*)d_in[6];
    const float* att0  = (const float*)d_in[7];
    const float* bias0 = (const float*)d_in[8];
    const float* W1    = (const float*)d_in[9];
    const float* b1    = (const float*)d_in[10];
    const float* We1   = (const float*)d_in[11];
    const float* att1  = (const float*)d_in[12];
    const float* bias1 = (const float*)d_in[13];
    const float* Wm1   = (const float*)d_in[14];
    const float* bm1   = (const float*)d_in[15];
    const float* Wm2   = (const float*)d_in[16];
    const float* bm2   = (const float*)d_in[17];

    int N = in_sizes[0] / 2;
    int E = in_sizes[1] / 2;

    const int TB = 256;
    int gE    = (E + TB - 1) / TB;
    int gN8   = (N * 8 + TB - 1) / TB;
    int gAgg  = (N * 32 + TB - 1) / TB;
    int gGemv = (N + 63) / 64;
    int nSB   = (N + 255) / 256;

    k_easum_hist<<<512, TB>>>(ei, (const float2*)ea, E);                // 0
    k_scan<<<nSB, 256>>>(N, E);                                         // 1
    k_scatter_z0<<<gE + gN8, TB>>>(ei, (const float2*)ea,
                                   (const float2*)x, W0, b0, N, E, gE); // 2
    // layer 0
    k_agg<<<gAgg, TB>>>(We0, att0, bias0, (const int*)0, N);            // 3 (profiled)
    k_gemv<<<gGemv, 128>>>(W1, b1, N, 0);                               // 4
    // layer 1
    k_agg<<<gAgg, TB>>>(We1, att1, bias1, dest, N);                     // 5
    k_gemv<<<gGemv, 128>>>(Wm1, (const float*)0, N, 1);                 // 6
    // edge scoring head
    k_edge<<<gAgg, TB>>>(Wm1, bm1, Wm2, bm2, (float*)d_out, N);         // 7
}

// round 12
// speedup vs baseline: 1.4172x; 1.0216x over previous
#include <cuda_runtime.h>
#include <math.h>

// Problem max sizes (N=50000, E=800000)
#define NMAX 50000
#define EMAX 800000

// ---- static device scratch (zero-initialized at module load; the
// pipeline re-zeroes cnt/tile/tilectr/easum each run in k_scatter_z0) ----
__device__ float  g_z[NMAX * 64];      // z of current layer (z0, then z1)
__device__ float  g_h[NMAX * 64];      // h of current layer
__device__ float  g_uv[NMAX * 64];     // [u | v] per node
__device__ __align__(16) float g_hdest[64];
__device__ double g_easum[2];
__device__ float  g_eamean[2];
// CSR by dst: packed edge payload {src, perm, ea.x(bits), ea.y(bits)}
__device__ int    g_cnt[NMAX];
__device__ int    g_rowptr[NMAX + 1];
__device__ int    g_rowcur[NMAX];
__device__ int4   g_epack[EMAX];
// decoupled-lookback scan state
__device__ unsigned long long g_tile[256];
__device__ int    g_tilectr;

// leaky relu, slope 0.2 < 1:  max(t, 0.2t) == leaky(t)
__device__ __forceinline__ float lrelu(float t) { return fmaxf(t, 0.2f * t); }

// ---- packed fp32x2 helpers (Blackwell FFMA2; used in k_gemv) ----
__device__ __forceinline__ unsigned long long pack2(float a, float b) {
    unsigned long long r;
    asm("mov.b64 %0, {%1, %2};" : "=l"(r) : "f"(a), "f"(b));
    return r;
}
__device__ __forceinline__ unsigned long long fma2(unsigned long long a,
                                                   unsigned long long b,
                                                   unsigned long long c) {
    unsigned long long d;
    asm("fma.rn.f32x2 %0, %1, %2, %3;" : "=l"(d) : "l"(a), "l"(b), "l"(c));
    return d;
}
__device__ __forceinline__ unsigned long long add2(unsigned long long a,
                                                   unsigned long long b) {
    unsigned long long d;
    asm("add.rn.f32x2 %0, %1, %2;" : "=l"(d) : "l"(a), "l"(b));
    return d;
}

// ============================================================
// 0) fused: edge_attr column sums (double) + dst histogram
// ============================================================
__global__ void k_easum_hist(const int* __restrict__ ei,
                             const float2* __restrict__ ea, int E) {
    double d0 = 0.0, d1 = 0.0;
    for (int i = blockIdx.x * blockDim.x + threadIdx.x; i < E;
         i += gridDim.x * blockDim.x) {
        float2 v = ea[i];
        d0 += (double)v.x; d1 += (double)v.y;
        atomicAdd(&g_cnt[ei[E + i]], 1);
    }
    __shared__ double sh0[256], sh1[256];
    int t = threadIdx.x;
    sh0[t] = d0; sh1[t] = d1;
    __syncthreads();
    for (int ofs = 128; ofs > 0; ofs >>= 1) {
        if (t < ofs) { sh0[t] += sh0[t + ofs]; sh1[t] += sh1[t + ofs]; }
        __syncthreads();
    }
    if (t == 0) { atomicAdd(&g_easum[0], sh0[0]); atomicAdd(&g_easum[1], sh1[0]); }
}

// ============================================================
// 1) exclusive scan of g_cnt (decoupled lookback) + eamean
// ============================================================
__global__ void __launch_bounds__(256) k_scan(int N, int E) {
    __shared__ int sbid;
    __shared__ int swsum[8];
    __shared__ int sexcl;
    if (threadIdx.x == 0) sbid = atomicAdd(&g_tilectr, 1);
    __syncthreads();
    int bid = sbid;
    if (bid == 0 && threadIdx.x < 2)
        g_eamean[threadIdx.x] = (float)(g_easum[threadIdx.x] / (double)E);

    int i = bid * 256 + threadIdx.x;
    int v = (i < N) ? g_cnt[i] : 0;
    int lane = threadIdx.x & 31, w = threadIdx.x >> 5;
    int s = v;
#pragma unroll
    for (int o = 1; o < 32; o <<= 1) {
        int t = __shfl_up_sync(0xffffffffu, s, o);
        if (lane >= o) s += t;
    }
    if (lane == 31) swsum[w] = s;
    __syncthreads();
    if (w == 0) {
        int ws = (lane < 8) ? swsum[lane] : 0;
#pragma unroll
        for (int o = 1; o < 8; o <<= 1) {
            int t = __shfl_up_sync(0xffffffffu, ws, o);
            if (lane >= o) ws += t;
        }
        if (lane < 8) swsum[lane] = ws;
    }
    __syncthreads();
    int incl = s + (w > 0 ? swsum[w - 1] : 0);
    int btotal = swsum[7];

    if (threadIdx.x == 0) {
        unsigned long long word = (bid == 0)
            ? ((2ull << 32) | (unsigned)btotal)
            : ((1ull << 32) | (unsigned)btotal);
        atomicExch(&g_tile[bid], word);
    }

    if (bid > 0 && w == 0) {
        int excl = 0;
        int look = bid - 1 - lane;
        for (;;) {
            unsigned long long word = (look >= 0)
                ? atomicAdd(&g_tile[look], 0ull) : (2ull << 32);
            unsigned st = (unsigned)(word >> 32);
            unsigned pend = __ballot_sync(0xffffffffu, st == 0u);
            if (pend) continue;
            unsigned pre = __ballot_sync(0xffffffffu, st == 2u);
            int fp = __ffs(pre) - 1;
            int val = (int)(word & 0xffffffffu);
            if (fp >= 0) {
                int contrib = (lane <= fp && look >= 0) ? val : 0;
#pragma unroll
                for (int o = 16; o > 0; o >>= 1)
                    contrib += __shfl_xor_sync(0xffffffffu, contrib, o);
                excl += contrib;
                break;
            } else {
                int contrib = (look >= 0) ? val : 0;
#pragma unroll
                for (int o = 16; o > 0; o >>= 1)
                    contrib += __shfl_xor_sync(0xffffffffu, contrib, o);
                excl += contrib;
                look -= 32;
            }
        }
        if (lane == 0) {
            atomicExch(&g_tile[bid], (2ull << 32) | (unsigned)(excl + btotal));
            sexcl = excl;
        }
    } else if (threadIdx.x == 0) {
        sexcl = 0;
    }
    __syncthreads();
    int excl = sexcl;
    if (i < N) {
        int ip = excl + incl;
        g_rowptr[i + 1] = ip;
        g_rowcur[i] = ip - v;
    }
    if (i == 0) g_rowptr[0] = 0;
}

// ============================================================
// 2) fused: packed CSR scatter + vectorized z0 = x@W0+b0
//    + re-zero cnt/tile/tilectr/easum for the next run
// ============================================================
__global__ void k_scatter_z0(const int* __restrict__ ei,
                             const float2* __restrict__ ea,
                             const float2* __restrict__ x,
                             const float* __restrict__ W0,
                             const float* __restrict__ b0,
                             int N, int E, int gE) {
    if ((int)blockIdx.x < gE) {
        int e = blockIdx.x * 256 + threadIdx.x;
        if (e < E) {
            int dst = ei[E + e];
            int pos = atomicAdd(&g_rowcur[dst], 1);
            float2 a = ea[e];
            g_epack[pos] = make_int4(ei[e], e, __float_as_int(a.x),
                                     __float_as_int(a.y));
        }
    } else {
        int i = (blockIdx.x - gE) * 256 + threadIdx.x;   // [0, N*8)
        if (i < N) g_cnt[i] = 0;
        if (i < 256) g_tile[i] = 0ull;
        if (i == 0) { g_tilectr = 0; g_easum[0] = 0.0; g_easum[1] = 0.0; }
        if (i < N * 8) {
            int n = i >> 3, j = (i & 7) * 8;
            float2 xv = x[n];
            float4 w0a = *(const float4*)&W0[j];
            float4 w0b = *(const float4*)&W0[j + 4];
            float4 w1a = *(const float4*)&W0[64 + j];
            float4 w1b = *(const float4*)&W0[64 + j + 4];
            float4 ba  = *(const float4*)&b0[j];
            float4 bb  = *(const float4*)&b0[j + 4];
            float4 r0, r1;
            r0.x = fmaf(xv.x, w0a.x, fmaf(xv.y, w1a.x, ba.x));
            r0.y = fmaf(xv.x, w0a.y, fmaf(xv.y, w1a.y, ba.y));
            r0.z = fmaf(xv.x, w0a.z, fmaf(xv.y, w1a.z, ba.z));
            r0.w = fmaf(xv.x, w0a.w, fmaf(xv.y, w1a.w, ba.w));
            r1.x = fmaf(xv.x, w0b.x, fmaf(xv.y, w1b.x, bb.x));
            r1.y = fmaf(xv.x, w0b.y, fmaf(xv.y, w1b.y, bb.y));
            r1.z = fmaf(xv.x, w0b.z, fmaf(xv.y, w1b.z, bb.z));
            r1.w = fmaf(xv.x, w0b.w, fmaf(xv.y, w1b.w, bb.w));
            *(float4*)&g_z[n * 64 + j]     = r0;
            *(float4*)&g_z[n * 64 + j + 4] = r1;
        }
    }
}

// ============================================================
// 3/5) GATv2 aggregation: fixed softmax reference (self-loop
// logit) + half-warp edge parallelism + epack prefetch.
// Scalar math (R10 form) + FMNMX leaky. 128-thread blocks to
// reduce block-tail imbalance.
// ============================================================
__global__ void __launch_bounds__(128)
k_agg(const float* __restrict__ We, const float* __restrict__ att,
      const float* __restrict__ bias, const int* __restrict__ destp, int N) {
    int dst = (blockIdx.x * blockDim.x + threadIdx.x) >> 5;
    int lane = threadIdx.x & 31;
    if (dst >= N) return;
    int half = lane >> 4;
    int q = lane & 15;
    int ch = q * 4;

    float4 We0 = *(const float4*)&We[ch];
    float4 We1 = *(const float4*)&We[64 + ch];
    float4 at  = *(const float4*)&att[ch];
    float4 zd  = __ldg((const float4*)&g_z[dst * 64 + ch]);

    // self-loop logit = fixed softmax reference m
    float eax = g_eamean[0], eay = g_eamean[1];
    float t, m;
    t = lrelu(zd.x + zd.x + fmaf(eax, We0.x, eay * We1.x)); m = t * at.x;
    t = lrelu(zd.y + zd.y + fmaf(eax, We0.y, eay * We1.y)); m = fmaf(t, at.y, m);
    t = lrelu(zd.z + zd.z + fmaf(eax, We0.z, eay * We1.z)); m = fmaf(t, at.z, m);
    t = lrelu(zd.w + zd.w + fmaf(eax, We0.w, eay * We1.w)); m = fmaf(t, at.w, m);
#pragma unroll
    for (int o = 4; o >= 1; o >>= 1) m += __shfl_xor_sync(0xffffffffu, m, o);

    float denom = (half == 0) ? 1.f : 0.f;
    float4 acc;
    acc.x = (half == 0) ? zd.x : 0.f;
    acc.y = (half == 0) ? zd.y : 0.f;
    acc.z = (half == 0) ? zd.z : 0.f;
    acc.w = (half == 0) ? zd.w : 0.f;

    int idx = g_rowptr[dst], end = g_rowptr[dst + 1];

    // prologue: prefetch first epack quad
    int4 pA, pB;
    if (idx + 4 <= end) {
        pA = g_epack[idx + half];
        pB = g_epack[idx + 2 + half];
    }
    while (idx + 4 <= end) {
        float4 zA = __ldg((const float4*)&g_z[pA.x * 64 + ch]);
        float4 zB = __ldg((const float4*)&g_z[pB.x * 64 + ch]);
        float eAx = __int_as_float(pA.z), eAy = __int_as_float(pA.w);
        float eBx = __int_as_float(pB.z), eBy = __int_as_float(pB.w);
        idx += 4;
        int4 nA, nB;
        if (idx + 4 <= end) {
            nA = g_epack[idx + half];
            nB = g_epack[idx + 2 + half];
        }

        float pa, pb;
        t = lrelu(zd.x + zA.x + fmaf(eAx, We0.x, eAy * We1.x)); pa = t * at.x;
        t = lrelu(zd.y + zA.y + fmaf(eAx, We0.y, eAy * We1.y)); pa = fmaf(t, at.y, pa);
        t = lrelu(zd.z + zA.z + fmaf(eAx, We0.z, eAy * We1.z)); pa = fmaf(t, at.z, pa);
        t = lrelu(zd.w + zA.w + fmaf(eAx, We0.w, eAy * We1.w)); pa = fmaf(t, at.w, pa);

        t = lrelu(zd.x + zB.x + fmaf(eBx, We0.x, eBy * We1.x)); pb = t * at.x;
        t = lrelu(zd.y + zB.y + fmaf(eBx, We0.y, eBy * We1.y)); pb = fmaf(t, at.y, pb);
        t = lrelu(zd.z + zB.z + fmaf(eBx, We0.z, eBy * We1.z)); pb = fmaf(t, at.z, pb);
        t = lrelu(zd.w + zB.w + fmaf(eBx, We0.w, eBy * We1.w)); pb = fmaf(t, at.w, pb);

#pragma unroll
        for (int o = 4; o >= 1; o >>= 1) {
            pa += __shfl_xor_sync(0xffffffffu, pa, o);
            pb += __shfl_xor_sync(0xffffffffu, pb, o);
        }
        float wa = __expf(pa - m);
        float wb = __expf(pb - m);
        denom += wa + wb;
        acc.x = fmaf(wa, zA.x, acc.x); acc.x = fmaf(wb, zB.x, acc.x);
        acc.y = fmaf(wa, zA.y, acc.y); acc.y = fmaf(wb, zB.y, acc.y);
        acc.z = fmaf(wa, zA.z, acc.z); acc.z = fmaf(wb, zB.z, acc.z);
        acc.w = fmaf(wa, zA.w, acc.w); acc.w = fmaf(wb, zB.w, acc.w);
        pA = nA; pB = nB;
    }
    // remainder: up to 3 edges, 2 at a time with validity guard
    for (; idx < end; idx += 2) {
        int e = idx + half;
        bool valid = e < end;
        int4 pR = g_epack[valid ? e : (end - 1)];
        float4 zA = __ldg((const float4*)&g_z[pR.x * 64 + ch]);
        float eAx = __int_as_float(pR.z), eAy = __int_as_float(pR.w);
        float pa;
        t = lrelu(zd.x + zA.x + fmaf(eAx, We0.x, eAy * We1.x)); pa = t * at.x;
        t = lrelu(zd.y + zA.y + fmaf(eAx, We0.y, eAy * We1.y)); pa = fmaf(t, at.y, pa);
        t = lrelu(zd.z + zA.z + fmaf(eAx, We0.z, eAy * We1.z)); pa = fmaf(t, at.z, pa);
        t = lrelu(zd.w + zA.w + fmaf(eAx, We0.w, eAy * We1.w)); pa = fmaf(t, at.w, pa);
#pragma unroll
        for (int o = 4; o >= 1; o >>= 1) pa += __shfl_xor_sync(0xffffffffu, pa, o);
        float wa = valid ? __expf(pa - m) : 0.f;
        denom += wa;
        acc.x = fmaf(wa, zA.x, acc.x);
        acc.y = fmaf(wa, zA.y, acc.y);
        acc.z = fmaf(wa, zA.z, acc.z);
        acc.w = fmaf(wa, zA.w, acc.w);
    }
    // merge half-warps (shared m -> plain addition)
    denom += __shfl_xor_sync(0xffffffffu, denom, 16);
    acc.x += __shfl_xor_sync(0xffffffffu, acc.x, 16);
    acc.y += __shfl_xor_sync(0xffffffffu, acc.y, 16);
    acc.z += __shfl_xor_sync(0xffffffffu, acc.z, 16);
    acc.w += __shfl_xor_sync(0xffffffffu, acc.w, 16);

    if (half == 0) {
        float inv = __fdividef(1.f, denom + 1e-16f);
        float4 b4 = *(const float4*)&bias[ch];
        float o; float4 h;
        o = fmaf(acc.x, inv, b4.x); h.x = (o > 0.f) ? o : expm1f(o);
        o = fmaf(acc.y, inv, b4.y); h.y = (o > 0.f) ? o : expm1f(o);
        o = fmaf(acc.z, inv, b4.z); h.z = (o > 0.f) ? o : expm1f(o);
        o = fmaf(acc.w, inv, b4.w); h.w = (o > 0.f) ? o : expm1f(o);
        *(float4*)&g_h[dst * 64 + ch] = h;
        if (destp && dst == destp[0]) *(float4*)&g_hdest[ch] = h;
    }
}

// ============================================================
// 4/6) register-tiled GEMM on device globals:
// mode 0: g_z[N,64]  = g_h[N,64] @ W (64x64 row-major) + bias
// mode 1: g_uv[N,64] = g_h[N,64] @ W' where
//         W'[k][j] = j<32 ? W[k*32+j] : W[(64+k)*32+j-32]   (no bias)
// ============================================================
__global__ void __launch_bounds__(128)
k_gemv(const float* __restrict__ W, const float* __restrict__ bias,
       int N, int mode) {
    __shared__ __align__(16) float sW[64 * 64];
    __shared__ __align__(16) float sA[64 * 68];

    for (int idx = threadIdx.x; idx < 4096; idx += 128) {
        int k = idx >> 6, j = idx & 63;
        sW[idx] = (mode == 0) ? W[idx]
                : ((j < 32) ? W[k * 32 + j] : W[(64 + k) * 32 + (j - 32)]);
    }
    int nbase = blockIdx.x * 64;
    for (int idx = threadIdx.x; idx < 64 * 16; idx += 128) {
        int n = idx >> 4, k4 = idx & 15;
        float4 av = (nbase + n < N)
            ? *(const float4*)&g_h[(nbase + n) * 64 + k4 * 4]
            : make_float4(0.f, 0.f, 0.f, 0.f);
        *(float4*)&sA[n * 68 + k4 * 4] = av;
    }
    __syncthreads();

    int cg = threadIdx.x & 7;        // channels cg*8 .. cg*8+7
    int ng = threadIdx.x >> 3;       // nodes ng*4 .. ng*4+3
    __align__(16) unsigned long long acc[4][4];
#pragma unroll
    for (int i = 0; i < 4; i++)
#pragma unroll
        for (int j = 0; j < 4; j++) acc[i][j] = 0ull;

    for (int k4 = 0; k4 < 16; k4++) {
        float4 a4[4];
#pragma unroll
        for (int i = 0; i < 4; i++)
            a4[i] = *(const float4*)&sA[(ng * 4 + i) * 68 + k4 * 4];
#pragma unroll
        for (int kk = 0; kk < 4; kk++) {
            int k = k4 * 4 + kk;
            ulonglong2 wl = *(const ulonglong2*)&sW[k * 64 + cg * 8];
            ulonglong2 wh = *(const ulonglong2*)&sW[k * 64 + cg * 8 + 4];
#pragma unroll
            for (int i = 0; i < 4; i++) {
                float a = (kk == 0) ? a4[i].x : (kk == 1) ? a4[i].y
                        : (kk == 2) ? a4[i].z : a4[i].w;
                unsigned long long aa = pack2(a, a);
                acc[i][0] = fma2(aa, wl.x, acc[i][0]);
                acc[i][1] = fma2(aa, wl.y, acc[i][1]);
                acc[i][2] = fma2(aa, wh.x, acc[i][2]);
                acc[i][3] = fma2(aa, wh.y, acc[i][3]);
            }
        }
    }
    if (mode == 0) {
        ulonglong2 b0 = *(const ulonglong2*)&bias[cg * 8];
        ulonglong2 b1v = *(const ulonglong2*)&bias[cg * 8 + 4];
#pragma unroll
        for (int i = 0; i < 4; i++) {
            acc[i][0] = add2(acc[i][0], b0.x);
            acc[i][1] = add2(acc[i][1], b0.y);
            acc[i][2] = add2(acc[i][2], b1v.x);
            acc[i][3] = add2(acc[i][3], b1v.y);
        }
    }
    float* C = (mode == 0) ? g_z : g_uv;
#pragma unroll
    for (int i = 0; i < 4; i++) {
        int n = nbase + ng * 4 + i;
        if (n < N) {
            *(float4*)&C[n * 64 + cg * 8]     = *(float4*)&acc[i][0];
            *(float4*)&C[n * 64 + cg * 8 + 4] = *(float4*)&acc[i][2];
        }
    }
}

// ============================================================
// 7) edge MLP, warp per dst node, 4 edges x 8 lanes per iteration,
// with epack prefetch pipelining. 128-thread blocks.
// ============================================================
__global__ void __launch_bounds__(128)
k_edge(const float* __restrict__ Wm1, const float* __restrict__ bm1,
       const float* __restrict__ Wm2, const float* __restrict__ bm2,
       float* __restrict__ out, int N) {
    __shared__ float sg[32];
    if (threadIdx.x < 32) {
        int j = threadIdx.x;
        float acc = bm1[j];
#pragma unroll
        for (int k = 0; k < 64; k++)
            acc = fmaf(g_hdest[k], Wm1[(128 + k) * 32 + j], acc);
        sg[j] = acc;
    }
    __syncthreads();

    int warp = (blockIdx.x * blockDim.x + threadIdx.x) >> 5;
    int lane = threadIdx.x & 31;
    if (warp >= N) return;
    int dst = warp;
    int g = lane >> 3;          // edge slot 0..3
    int l = lane & 7;           // channel block: channels [4l, 4l+4)

    float4 v4 = __ldg((const float4*)&g_uv[dst * 64 + 32 + l * 4]);
    float4 gv = *(const float4*)&sg[l * 4];
    float4 w0 = __ldg(&((const float4*)&Wm1[192 * 32])[l]);
    float4 w1 = __ldg(&((const float4*)&Wm1[193 * 32])[l]);
    float4 w2 = __ldg(&((const float4*)Wm2)[l]);
    float bm2v = bm2[0];
    float bx = v4.x + gv.x, by = v4.y + gv.y;
    float bz = v4.z + gv.z, bw = v4.w + gv.w;

    int start = g_rowptr[dst], end = g_rowptr[dst + 1];
    if (start >= end) return;
    int e0 = start + g;
    int4 pk = g_epack[(e0 < end) ? e0 : (end - 1)];
    for (int idx = start; idx < end; idx += 4) {
        int e = idx + g;
        bool valid = e < end;
        float4 u4 = __ldg((const float4*)&g_uv[pk.x * 64 + l * 4]);
        float ax = __int_as_float(pk.z), ay = __int_as_float(pk.w);
        int perm = pk.y;
        int en = idx + 4 + g;
        if (idx + 4 < end) pk = g_epack[(en < end) ? en : (end - 1)];

        float m0 = u4.x + bx + fmaf(ax, w0.x, ay * w1.x);
        float m1 = u4.y + by + fmaf(ax, w0.y, ay * w1.y);
        float m2 = u4.z + bz + fmaf(ax, w0.z, ay * w1.z);
        float m3 = u4.w + bw + fmaf(ax, w0.w, ay * w1.w);
        m0 = fmaxf(m0, 0.f); m1 = fmaxf(m1, 0.f);
        m2 = fmaxf(m2, 0.f); m3 = fmaxf(m3, 0.f);
        float s = fmaf(m0, w2.x, fmaf(m1, w2.y, fmaf(m2, w2.z, m3 * w2.w)));
        s += __shfl_xor_sync(0xffffffffu, s, 4);
        s += __shfl_xor_sync(0xffffffffu, s, 2);
        s += __shfl_xor_sync(0xffffffffu, s, 1);
        if (valid && l == 0) out[perm] = s + bm2v;
    }
}

// ============================================================
extern "C" void kernel_launch(void* const* d_in, const int* in_sizes, int n_in,
                              void* d_out, int out_size) {
    const float* x     = (const float*)d_in[0];
    const int*   ei    = (const int*)d_in[1];
    const float* ea    = (const float*)d_in[2];
    const int*   dest  = (const int*)d_in[3];
    const float* W0    = (const float*)d_in[4];
    const float* b0    = (const float*)d_in[5];
    const float* We0   = (const float*)d_in[6];
    const float* att0  = (const float*)d_in[7];
    const float* bias0 = (const float*)d_in[8];
    const float* W1    = (const float*)d_in[9];
    const float* b1    = (const float*)d_in[10];
    const float* We1   = (const float*)d_in[11];
    const float* att1  = (const float*)d_in[12];
    const float* bias1 = (const float*)d_in[13];
    const float* Wm1   = (const float*)d_in[14];
    const float* bm1   = (const float*)d_in[15];
    const float* Wm2   = (const float*)d_in[16];
    const float* bm2   = (const float*)d_in[17];

    int N = in_sizes[0] / 2;
    int E = in_sizes[1] / 2;

    const int TB = 256;
    int gE    = (E + TB - 1) / TB;
    int gN8   = (N * 8 + TB - 1) / TB;
    int gAgg  = (N * 32 + 127) / 128;   // 128-thread blocks, warp per dst
    int gGemv = (N + 63) / 64;
    int nSB   = (N + 255) / 256;

    k_easum_hist<<<512, TB>>>(ei, (const float2*)ea, E);                // 0
    k_scan<<<nSB, 256>>>(N, E);                                         // 1
    k_scatter_z0<<<gE + gN8, TB>>>(ei, (const float2*)ea,
                                   (const float2*)x, W0, b0, N, E, gE); // 2
    // layer 0
    k_agg<<<gAgg, 128>>>(We0, att0, bias0, (const int*)0, N);           // 3 (profiled)
    k_gemv<<<gGemv, 128>>>(W1, b1, N, 0);                               // 4
    // layer 1
    k_agg<<<gAgg, 128>>>(We1, att1, bias1, dest, N);                    // 5
    k_gemv<<<gGemv, 128>>>(Wm1, (const float*)0, N, 1);                 // 6
    // edge scoring head
    k_edge<<<gAgg, 128>>>(Wm1, bm1, Wm2, bm2, (float*)d_out, N);        // 7
}